// round 14
// baseline (speedup 1.0000x reference)
#include <cuda_runtime.h>
#include <cuda_bf16.h>
#include <math.h>
#include <stdint.h>

#define NB 8
#define NC 128
#define NH 8
#define HD 16
#define KVL 85

#define TSTR 272
#define TILEB (128 * TSTR)     // 34816
#define K8STR 272
#define K8TILE (96 * K8STR)    // 26112: rows=kv(96 pad), cols=8 heads x 16c
#define V8STR 208
#define V8TILE (128 * V8STR)   // 26624: rows=8 heads x 16c, cols=j(96 pad 104)

__device__ __align__(16) float d_tab[128 * 64];
__device__ __align__(16) float d_tabT[64 * 128];
__device__ __align__(16) float d_tabR[8 * 64];
__device__ __align__(16) float d_y1[NB * KVL * NC];
__device__ __align__(16) float d_pwT[128 * 128];
__device__ __align__(16) float d_WkvT[128 * 256];
__device__ __align__(16) unsigned char d_wqh[TILEB];
__device__ __align__(16) unsigned char d_wql[TILEB];
__device__ __align__(16) unsigned char d_wph[TILEB];
__device__ __align__(16) unsigned char d_wpl[TILEB];
__device__ __align__(16) unsigned char d_kth[NB * K8TILE];
__device__ __align__(16) unsigned char d_ktl[NB * K8TILE];
__device__ __align__(16) unsigned char d_vth[NB * V8TILE];
__device__ __align__(16) unsigned char d_vtl[NB * V8TILE];

__device__ __forceinline__ uint32_t bf2u(__nv_bfloat162 v) {
    return ((uint32_t)__bfloat16_as_ushort(v.y) << 16) | (uint32_t)__bfloat16_as_ushort(v.x);
}
__device__ __forceinline__ void bfsplit(float v0, float v1, uint32_t& hi, uint32_t& lo) {
    __nv_bfloat162 hh = __floats2bfloat162_rn(v0, v1);
    __nv_bfloat162 ll = __floats2bfloat162_rn(v0 - __bfloat162float(hh.x),
                                              v1 - __bfloat162float(hh.y));
    hi = bf2u(hh); lo = bf2u(ll);
}

// ---------------- K0: tables + transposes + weight split + KV zero ----------
__global__ void k_prep(const float* __restrict__ pw, const float* __restrict__ Wkv,
                       const float* __restrict__ Wq, const float* __restrict__ Wp) {
    int idx = blockIdx.x * 256 + threadIdx.x;
    if (idx < 8192) {
        int yv = idx >> 6, j = idx & 63, i = j & 31;
        float inv = powf(10000.0f, -(2.0f * (float)i) / 64.0f);
        float a = (float)yv * inv;
        d_tab[idx] = (j < 32) ? sinf(a) : cosf(a);
    } else if (idx < 16384) {
        int e = idx - 8192;
        int j = e >> 7, p = e & 127, i = j & 31;
        float inv = powf(10000.0f, -(2.0f * (float)i) / 64.0f);
        float a = (float)p * inv;
        d_tabT[e] = (j < 32) ? sinf(a) : cosf(a);
    } else if (idx < 16896) {
        int e = idx - 16384;
        int bin = e >> 6, j = e & 63, i = j & 31;
        float inv = powf(10000.0f, -(2.0f * (float)i) / 64.0f);
        float s = 0.0f;
        for (int t = 0; t < 16; ++t) {
            float a = (float)(bin * 16 + t) * inv;
            s += (j < 32) ? sinf(a) : cosf(a);
        }
        d_tabR[e] = s;
    } else if (idx < 33280) {
        int e = idx - 16896;
        d_pwT[e] = pw[(e & 127) * 128 + (e >> 7)];
    } else if (idx < 66048) {
        int e = idx - 33280;
        d_WkvT[e] = Wkv[(e & 255) * 128 + (e >> 8)];
    } else if (idx < 98816) {
        int i = idx - 66048;
        const float* W; unsigned char *H, *L; int e;
        if (i < 16384) { W = Wq; H = d_wqh; L = d_wql; e = i; }
        else           { W = Wp; H = d_wph; L = d_wpl; e = i - 16384; }
        int o = e >> 7, c = e & 127;
        float v = W[e];
        __nv_bfloat16 h = __float2bfloat16(v);
        float r = v - __bfloat162float(h);
        uint32_t off = (uint32_t)(o * TSTR + c * 2);
        *(__nv_bfloat16*)(H + off) = h;
        *(__nv_bfloat16*)(L + off) = __float2bfloat16(r);
    } else if (idx < 98816 + 52224) {
        ((uint32_t*)d_kth)[idx - 98816] = 0;
    } else if (idx < 98816 + 104448) {
        ((uint32_t*)d_ktl)[idx - 98816 - 52224] = 0;
    } else if (idx < 98816 + 104448 + 53248) {
        ((uint32_t*)d_vth)[idx - 98816 - 104448] = 0;
    } else if (idx < 98816 + 104448 + 106496) {
        ((uint32_t*)d_vtl)[idx - 98816 - 104448 - 53248] = 0;
    }
}

// ---------------- K1: ASPP pooling + depthwise conv (validated) -------------
__global__ void k_pool_dw(const float* __restrict__ x, const float* __restrict__ dw) {
    __shared__ float pm[64];
    __shared__ float g4[16];
    __shared__ float g2[4];
    __shared__ float g1[1];
    int tid = threadIdx.x;
    int b = blockIdx.x >> 7, c = blockIdx.x & 127;
    if (tid < 64) pm[tid] = 0.0f;
    __syncthreads();
    int r = tid >> 1, hf = tid & 1;
    const float4* xr = (const float4*)(x + ((size_t)(b * NC + c) << 14) + (r << 7) + (hf << 6));
    float sbin[4] = {0.0f, 0.0f, 0.0f, 0.0f};
#pragma unroll
    for (int q = 0; q < 16; ++q) {
        float4 v = xr[q];
        sbin[q >> 2] += (v.x + v.y) + (v.z + v.w);
    }
    int by = r >> 4;
#pragma unroll
    for (int t = 0; t < 4; ++t) atomicAdd(&pm[by * 8 + hf * 4 + t], sbin[t]);
    __syncthreads();
    if (tid < 64) {
        int byy = tid >> 3, bx = tid & 7;
        float pe = (c < 64) ? d_tabR[byy * 64 + c] : d_tabR[bx * 64 + (c - 64)];
        pm[tid] = (pm[tid] + 16.0f * pe) * (1.0f / 256.0f);
    }
    __syncthreads();
    if (tid < 16) {
        int i = tid >> 2, j = tid & 3;
        g4[tid] = 0.25f * (pm[(2 * i) * 8 + 2 * j] + pm[(2 * i) * 8 + 2 * j + 1] +
                           pm[(2 * i + 1) * 8 + 2 * j] + pm[(2 * i + 1) * 8 + 2 * j + 1]);
    } else if (tid < 20) {
        int t = tid - 16, i = t >> 1, j = t & 1;
        float s = 0.0f;
        for (int yy = 0; yy < 4; ++yy)
            for (int xq = 0; xq < 4; ++xq) s += pm[(4 * i + yy) * 8 + 4 * j + xq];
        g2[t] = s * (1.0f / 16.0f);
    } else if (tid == 20) {
        float s = 0.0f;
        for (int q = 0; q < 64; ++q) s += pm[q];
        g1[0] = s * (1.0f / 64.0f);
    }
    __syncthreads();
    if (tid < KVL) {
        float wv[9];
#pragma unroll
        for (int q = 0; q < 9; ++q) wv[q] = dw[c * 9 + q];
        const float* g; int s, ly, lx;
        if (tid < 64)      { g = pm; s = 8; ly = tid >> 3;        lx = tid & 7; }
        else if (tid < 80) { int t = tid - 64; g = g4; s = 4; ly = t >> 2; lx = t & 3; }
        else if (tid < 84) { int t = tid - 80; g = g2; s = 2; ly = t >> 1; lx = t & 1; }
        else               { g = g1; s = 1; ly = 0; lx = 0; }
        float a = 0.0f;
#pragma unroll
        for (int ky = 0; ky < 3; ++ky) {
            int iy = ly + ky - 1;
            bool oky = (iy >= 0) && (iy < s);
#pragma unroll
            for (int kx = 0; kx < 3; ++kx) {
                int ix = lx + kx - 1;
                if (oky && ix >= 0 && ix < s) a += g[iy * s + ix] * wv[ky * 3 + kx];
            }
        }
        d_y1[((size_t)b * KVL + tid) * NC + c] = a;
    }
}

// ---------------- K2: pointwise -> LN -> GELU -> KV proj (8-head tiles) -----
__global__ void k_pw_ln_kv(const float* __restrict__ lnw, const float* __restrict__ lnb) {
    __shared__ float ycol[128];
    __shared__ float part[256];
    __shared__ float zs[128];
    __shared__ float red[2];
    int tid = threadIdx.x;
    int b = blockIdx.x / KVL;
    int row = blockIdx.x - b * KVL;
    if (tid < 128) ycol[tid] = d_y1[((size_t)b * KVL + row) * NC + tid];
    __syncthreads();
    {
        int o = tid & 127, half = tid >> 7;
        const float* wc = d_pwT + (half << 6) * 128 + o;
        const float* yc = ycol + (half << 6);
        float a = 0.0f;
#pragma unroll 8
        for (int ci = 0; ci < 64; ++ci) a += wc[ci * 128] * yc[ci];
        part[tid] = a;
    }
    __syncthreads();
    if (tid < 128) zs[tid] = part[tid] + part[tid + 128];
    __syncthreads();
    if (tid < 32) {
        float s = zs[tid] + zs[tid + 32] + zs[tid + 64] + zs[tid + 96];
#pragma unroll
        for (int o = 16; o; o >>= 1) s += __shfl_xor_sync(0xffffffffu, s, o);
        if (tid == 0) red[0] = s * (1.0f / 128.0f);
    }
    __syncthreads();
    float mu = red[0];
    if (tid < 32) {
        float s = 0.0f;
#pragma unroll
        for (int q = 0; q < 4; ++q) { float dd = zs[tid + 32 * q] - mu; s += dd * dd; }
#pragma unroll
        for (int o = 16; o; o >>= 1) s += __shfl_xor_sync(0xffffffffu, s, o);
        if (tid == 0) red[1] = s * (1.0f / 128.0f);
    }
    __syncthreads();
    float rstd = rsqrtf(red[1] + 1e-5f);
    if (tid < 128) {
        float zn = (zs[tid] - mu) * rstd * lnw[tid] + lnb[tid];
        zs[tid] = 0.5f * zn * (1.0f + erff(zn * 0.70710678118654752f));
    }
    __syncthreads();
    float a = 0.0f;
    const float* wc = d_WkvT + tid;
#pragma unroll 8
    for (int ci = 0; ci < 128; ++ci) a += wc[ci * 256] * zs[ci];
    __nv_bfloat16 h = __float2bfloat16(a);
    __nv_bfloat16 l = __float2bfloat16(a - __bfloat162float(h));
    if (tid < 128) {       // K: rows=kv j, cols = head*16 + d
        int m = tid >> 4, d = tid & 15;
        uint32_t off = ((uint32_t)b * 96 + row) * K8STR + m * 32 + d * 2;
        *(__nv_bfloat16*)(d_kth + off) = h;
        *(__nv_bfloat16*)(d_ktl + off) = l;
    } else {               // V^T: rows = head*16 + d, cols = j
        int cc = tid - 128;
        int m = cc >> 4, d = cc & 15;
        uint32_t off = ((uint32_t)b * 128 + m * 16 + d) * V8STR + row * 2;
        *(__nv_bfloat16*)(d_vth + off) = h;
        *(__nv_bfloat16*)(d_vtl + off) = l;
    }
}

// ---------------- K3: fused main — HMMA, Q in registers, 1024 threads -------
#define OXH 0
#define OXL TILEB              // 34816
#define OW  (2 * TILEB)        // 69632: Wq/Wproj hi (lo at +TILEB); KV overlays
#define OK8H OW                // 69632
#define OK8L (OK8H + K8TILE)   // 95744
#define OV8H (OK8L + K8TILE)   // 121856
#define OV8L (OV8H + V8TILE)   // 148480
#define OBI  (OV8L + V8TILE)   // 175104
#define SMB  (OBI + 512 + 64)

#define LDMX4(r0, r1, r2, r3, a) \
    asm volatile("ldmatrix.sync.aligned.m8n8.x4.shared.b16 {%0,%1,%2,%3}, [%4];" \
        : "=r"(r0), "=r"(r1), "=r"(r2), "=r"(r3) : "r"(a))
#define LDMX2(r0, r1, a) \
    asm volatile("ldmatrix.sync.aligned.m8n8.x2.shared.b16 {%0,%1}, [%2];" \
        : "=r"(r0), "=r"(r1) : "r"(a))
#define MMA16816(d, a0, a1, a2, a3, b0, b1) \
    asm volatile("mma.sync.aligned.m16n8k16.row.col.f32.bf16.bf16.f32 " \
        "{%0,%1,%2,%3}, {%4,%5,%6,%7}, {%8,%9}, {%0,%1,%2,%3};" \
        : "+f"((d)[0]), "+f"((d)[1]), "+f"((d)[2]), "+f"((d)[3]) \
        : "r"(a0), "r"(a1), "r"(a2), "r"(a3), "r"(b0), "r"(b1))

// D[m=A-rows][n=B-rows]: 32 warps, mt=w&7 (16 A-rows), nq=w>>3 (32 B-rows)
__device__ __forceinline__ void hmma_gemm(uint32_t sb, uint32_t aBase, uint32_t bBase,
                                          int w, int lane, float D[4][4]) {
#pragma unroll
    for (int n = 0; n < 4; ++n)
#pragma unroll
        for (int q = 0; q < 4; ++q) D[n][q] = 0.0f;
    int mt = w & 7, nq = w >> 3;
    int sub = lane >> 3, r = lane & 7;
    uint32_t aH = sb + aBase + (uint32_t)((mt * 16 + (sub & 1) * 8 + r) * TSTR + (sub >> 1) * 16);
    uint32_t aL = aH + TILEB;
    int bl = lane & 15;
    uint32_t bH = sb + bBase + (uint32_t)((nq * 32 + (bl & 7)) * TSTR + (bl >> 3) * 16);
    uint32_t bL = bH + TILEB;
#pragma unroll
    for (int kc = 0; kc < 8; ++kc) {
        uint32_t ah0, ah1, ah2, ah3, al0, al1, al2, al3;
        LDMX4(ah0, ah1, ah2, ah3, aH + kc * 32);
        LDMX4(al0, al1, al2, al3, aL + kc * 32);
#pragma unroll
        for (int n = 0; n < 4; ++n) {
            uint32_t bh0, bh1, bl0, bl1;
            LDMX2(bh0, bh1, bH + n * (8 * TSTR) + kc * 32);
            LDMX2(bl0, bl1, bL + n * (8 * TSTR) + kc * 32);
            MMA16816(D[n], ah0, ah1, ah2, ah3, bh0, bh1);
            MMA16816(D[n], al0, al1, al2, al3, bh0, bh1);
            MMA16816(D[n], ah0, ah1, ah2, ah3, bl0, bl1);
        }
    }
}

__global__ void __launch_bounds__(1024, 1)
k_main(const float* __restrict__ x, const float* __restrict__ bproj,
       float* __restrict__ out) {
    extern __shared__ char smc[];
    uint32_t sb;
    asm("{ .reg .u64 t; cvta.to.shared.u64 t, %1; cvt.u32.u64 %0, t; }" : "=r"(sb) : "l"(smc));
    int tid = threadIdx.x, w = tid >> 5, lane = tid & 31;
    int b = blockIdx.x >> 7, y = blockIdx.x & 127;

    if (tid < 128) ((float*)(smc + OBI))[tid] = bproj[tid];
    {   // Wq tiles -> OW
        const float4* h4 = (const float4*)d_wqh;
        const float4* l4 = (const float4*)d_wql;
        float4* wh = (float4*)(smc + OW);
        float4* wl = (float4*)(smc + OW + TILEB);
        for (int i = tid; i < TILEB / 16; i += 1024) { wh[i] = h4[i]; wl[i] = l4[i]; }
    }
    {   // Xp bf16 split tiles: rows=px, cols=c
        int p = tid & 127;
        int yoff = y << 7;
        for (int g = tid >> 7; g < 64; g += 8) {
            int c0 = g * 2, c1 = c0 + 1;
            float v0 = x[((size_t)(b * NC + c0) << 14) + yoff + p];
            float v1 = x[((size_t)(b * NC + c1) << 14) + yoff + p];
            v0 += (c0 < 64) ? d_tab[y * 64 + c0] : d_tabT[(c0 - 64) * 128 + p];
            v1 += (c1 < 64) ? d_tab[y * 64 + c1] : d_tabT[(c1 - 64) * 128 + p];
            uint32_t hi, lo;
            bfsplit(v0, v1, hi, lo);
            uint32_t off = (uint32_t)(p * TSTR + c0 * 2);
            *(uint32_t*)(smc + OXH + off) = hi;
            *(uint32_t*)(smc + OXL + off) = lo;
        }
    }
    __syncthreads();

    float D[4][4];
    // ---- Q-GEMM: D[px][c] (A = X, B = Wq); Q stays in registers ----
    hmma_gemm(sb, OXH, OW, w, lane, D);

    // pack Q A-frags (bf16 hi/lo, x0.25) for this warp's two heads directly from D
    uint32_t qh[2][4], ql[2][4];
#pragma unroll
    for (int t = 0; t < 2; ++t) {
        bfsplit(D[2 * t][0] * 0.25f, D[2 * t][1] * 0.25f, qh[t][0], ql[t][0]);
        bfsplit(D[2 * t][2] * 0.25f, D[2 * t][3] * 0.25f, qh[t][1], ql[t][1]);
        bfsplit(D[2 * t + 1][0] * 0.25f, D[2 * t + 1][1] * 0.25f, qh[t][2], ql[t][2]);
        bfsplit(D[2 * t + 1][2] * 0.25f, D[2 * t + 1][3] * 0.25f, qh[t][3], ql[t][3]);
    }
    __syncthreads();   // all Wq/X reads done; OW region free for KV

    {   // fill K/V (all 8 heads) into the dead-Wq region
        const float4* kh = (const float4*)(d_kth + (size_t)b * K8TILE);
        const float4* kl = (const float4*)(d_ktl + (size_t)b * K8TILE);
        const float4* vh = (const float4*)(d_vth + (size_t)b * V8TILE);
        const float4* vl = (const float4*)(d_vtl + (size_t)b * V8TILE);
        float4* dkh = (float4*)(smc + OK8H);
        float4* dkl = (float4*)(smc + OK8L);
        float4* dvh = (float4*)(smc + OV8H);
        float4* dvl = (float4*)(smc + OV8L);
        for (int i = tid; i < K8TILE / 16; i += 1024) { dkh[i] = kh[i]; dkl[i] = kl[i]; }
        for (int i = tid; i < V8TILE / 16; i += 1024) { dvh[i] = vh[i]; dvl[i] = vl[i]; }
    }
    __syncthreads();

    // ---- attention: 2 tasks/warp = heads 2nq, 2nq+1 on px-tile mt ----
    int nq = w >> 3, mt = w & 7;
    int bl = lane & 15, q = lane & 3, rr = lane >> 2;
#pragma unroll 1
    for (int t = 0; t < 2; ++t) {
        int h = nq * 2 + t;
        uint32_t kbase = sb + OK8H + (uint32_t)((bl & 7) * K8STR + h * 32 + (bl >> 3) * 16);
        uint32_t vbase = sb + OV8H + (uint32_t)((h * 16 + (bl & 7)) * V8STR + (bl >> 3) * 16);
        float o0[4] = {0, 0, 0, 0}, o1[4] = {0, 0, 0, 0};
        float sr = 0.0f, sr8 = 0.0f;
#pragma unroll
        for (int ks = 0; ks < 6; ++ks) {
            float P0[4] = {0, 0, 0, 0}, P1[4] = {0, 0, 0, 0};
            uint32_t kh0, kh1, kl0, kl1;
            LDMX2(kh0, kh1, kbase + (2 * ks) * (8 * K8STR));
            LDMX2(kl0, kl1, kbase + (2 * ks) * (8 * K8STR) + (OK8L - OK8H));
            MMA16816(P0, qh[t][0], qh[t][1], qh[t][2], qh[t][3], kh0, kh1);
            MMA16816(P0, ql[t][0], ql[t][1], ql[t][2], ql[t][3], kh0, kh1);
            MMA16816(P0, qh[t][0], qh[t][1], qh[t][2], qh[t][3], kl0, kl1);
            LDMX2(kh0, kh1, kbase + (2 * ks + 1) * (8 * K8STR));
            LDMX2(kl0, kl1, kbase + (2 * ks + 1) * (8 * K8STR) + (OK8L - OK8H));
            MMA16816(P1, qh[t][0], qh[t][1], qh[t][2], qh[t][3], kh0, kh1);
            MMA16816(P1, ql[t][0], ql[t][1], ql[t][2], ql[t][3], kh0, kh1);
            MMA16816(P1, qh[t][0], qh[t][1], qh[t][2], qh[t][3], kl0, kl1);
            float e00 = __expf(P0[0]), e01 = __expf(P0[1]);
            float e02 = __expf(P0[2]), e03 = __expf(P0[3]);
            float e10 = __expf(P1[0]), e11 = __expf(P1[1]);
            float e12 = __expf(P1[2]), e13 = __expf(P1[3]);
            sr += (e00 + e01) + (e10 + e11);
            sr8 += (e02 + e03) + (e12 + e13);
            uint32_t ah0, ah1, ah2, ah3, al0, al1, al2, al3;
            bfsplit(e00, e01, ah0, al0);
            bfsplit(e02, e03, ah1, al1);
            bfsplit(e10, e11, ah2, al2);
            bfsplit(e12, e13, ah3, al3);
            uint32_t vh0, vh1, vl0, vl1;
            LDMX2(vh0, vh1, vbase + ks * 32);
            LDMX2(vl0, vl1, vbase + ks * 32 + (OV8L - OV8H));
            MMA16816(o0, ah0, ah1, ah2, ah3, vh0, vh1);
            MMA16816(o0, al0, al1, al2, al3, vh0, vh1);
            MMA16816(o0, ah0, ah1, ah2, ah3, vl0, vl1);
            LDMX2(vh0, vh1, vbase + 8 * V8STR + ks * 32);
            LDMX2(vl0, vl1, vbase + 8 * V8STR + ks * 32 + (OV8L - OV8H));
            MMA16816(o1, ah0, ah1, ah2, ah3, vh0, vh1);
            MMA16816(o1, al0, al1, al2, al3, vh0, vh1);
            MMA16816(o1, ah0, ah1, ah2, ah3, vl0, vl1);
        }
        sr += __shfl_xor_sync(0xffffffffu, sr, 1);
        sr += __shfl_xor_sync(0xffffffffu, sr, 2);
        sr8 += __shfl_xor_sync(0xffffffffu, sr8, 1);
        sr8 += __shfl_xor_sync(0xffffffffu, sr8, 2);
        float ir = 1.0f / (sr - 11.0f), ir8 = 1.0f / (sr8 - 11.0f);
        int px0 = mt * 16 + rr;
        int c0 = h * 16 + q * 2;
        uint32_t hi, lo;
        bfsplit(o0[0] * ir, o0[1] * ir, hi, lo);
        *(uint32_t*)(smc + OXH + px0 * TSTR + c0 * 2) = hi;
        *(uint32_t*)(smc + OXL + px0 * TSTR + c0 * 2) = lo;
        bfsplit(o0[2] * ir8, o0[3] * ir8, hi, lo);
        *(uint32_t*)(smc + OXH + (px0 + 8) * TSTR + c0 * 2) = hi;
        *(uint32_t*)(smc + OXL + (px0 + 8) * TSTR + c0 * 2) = lo;
        bfsplit(o1[0] * ir, o1[1] * ir, hi, lo);
        *(uint32_t*)(smc + OXH + px0 * TSTR + (c0 + 8) * 2) = hi;
        *(uint32_t*)(smc + OXL + px0 * TSTR + (c0 + 8) * 2) = lo;
        bfsplit(o1[2] * ir8, o1[3] * ir8, hi, lo);
        *(uint32_t*)(smc + OXH + (px0 + 8) * TSTR + (c0 + 8) * 2) = hi;
        *(uint32_t*)(smc + OXL + (px0 + 8) * TSTR + (c0 + 8) * 2) = lo;
    }
    __syncthreads();   // O complete; KV dead
    {   // Wproj tiles
        const float4* h4 = (const float4*)d_wph;
        const float4* l4 = (const float4*)d_wpl;
        float4* wh = (float4*)(smc + OW);
        float4* wl = (float4*)(smc + OW + TILEB);
        for (int i = tid; i < TILEB / 16; i += 1024) { wh[i] = h4[i]; wl[i] = l4[i]; }
    }
    __syncthreads();

    // ---- out-proj GEMM: D[px][c] (A = O, B = Wproj) + bias + store ----
    hmma_gemm(sb, OXH, OW, w, lane, D);
    {
        const float* bias = (const float*)(smc + OBI);
        int px0 = mt * 16 + rr;
        float* og = out + (((size_t)b * NC) << 14) + (y << 7);
#pragma unroll
        for (int n = 0; n < 4; ++n) {
            int c0 = nq * 32 + n * 8 + q * 2;
            float b0 = bias[c0], b1 = bias[c0 + 1];
            float* p0 = og + (((size_t)c0) << 14);
            float* p1 = og + (((size_t)(c0 + 1)) << 14);
            p0[px0] = D[n][0] + b0;
            p1[px0] = D[n][1] + b1;
            p0[px0 + 8] = D[n][2] + b0;
            p1[px0 + 8] = D[n][3] + b1;
        }
    }
}

// ----------------------------------------------------------------------------
extern "C" void kernel_launch(void* const* d_in, const int* in_sizes, int n_in,
                              void* d_out, int out_size) {
    const float* x     = (const float*)d_in[0];
    const float* Wq    = (const float*)d_in[1];
    const float* Wkv   = (const float*)d_in[2];
    const float* Wproj = (const float*)d_in[3];
    const float* bproj = (const float*)d_in[4];
    const float* dw    = (const float*)d_in[5];
    const float* pw    = (const float*)d_in[6];
    const float* lnw   = (const float*)d_in[7];
    const float* lnb   = (const float*)d_in[8];
    float* out = (float*)d_out;

    cudaFuncSetAttribute(k_main, cudaFuncAttributeMaxDynamicSharedMemorySize, SMB);

    k_prep<<<1210, 256>>>(pw, Wkv, Wq, Wproj);
    k_pool_dw<<<NB * NC, 256>>>(x, dw);
    k_pw_ln_kv<<<NB * KVL, 256>>>(lnw, lnb);
    k_main<<<NB * 128, 1024, SMB>>>(x, bproj, out);
}

// round 15
// speedup vs baseline: 1.0228x; 1.0228x over previous
#include <cuda_runtime.h>
#include <cuda_bf16.h>
#include <math.h>
#include <stdint.h>

#define NB 8
#define NC 128
#define NH 8
#define HD 16
#define KVL 85

#define TSTR 272
#define TILEB (128 * TSTR)     // 34816
#define K8STR 272
#define K8TILE (96 * K8STR)    // 26112: rows=kv(96 pad), cols=8 heads x 16c
#define V8STR 208
#define V8TILE (128 * V8STR)   // 26624: rows=8 heads x 16c, cols=j(96 pad 104)

__device__ __align__(16) float d_tab[128 * 64];
__device__ __align__(16) float d_tabT[64 * 128];
__device__ __align__(16) float d_tabR[8 * 64];
__device__ __align__(16) float d_y1[NB * KVL * NC];
__device__ __align__(16) float d_pwT[128 * 128];
__device__ __align__(16) float d_WkvT[128 * 256];
__device__ __align__(16) unsigned char d_wqh[TILEB];
__device__ __align__(16) unsigned char d_wql[TILEB];
__device__ __align__(16) unsigned char d_wph[TILEB];
__device__ __align__(16) unsigned char d_wpl[TILEB];
__device__ __align__(16) unsigned char d_kth[NB * K8TILE];
__device__ __align__(16) unsigned char d_ktl[NB * K8TILE];
__device__ __align__(16) unsigned char d_vth[NB * V8TILE];
__device__ __align__(16) unsigned char d_vtl[NB * V8TILE];

__device__ __forceinline__ uint32_t bf2u(__nv_bfloat162 v) {
    return ((uint32_t)__bfloat16_as_ushort(v.y) << 16) | (uint32_t)__bfloat16_as_ushort(v.x);
}
__device__ __forceinline__ void bfsplit(float v0, float v1, uint32_t& hi, uint32_t& lo) {
    __nv_bfloat162 hh = __floats2bfloat162_rn(v0, v1);
    __nv_bfloat162 ll = __floats2bfloat162_rn(v0 - __bfloat162float(hh.x),
                                              v1 - __bfloat162float(hh.y));
    hi = bf2u(hh); lo = bf2u(ll);
}

// ---------------- K0: tables + transposes + weight split + KV zero ----------
__global__ void k_prep(const float* __restrict__ pw, const float* __restrict__ Wkv,
                       const float* __restrict__ Wq, const float* __restrict__ Wp) {
    int idx = blockIdx.x * 256 + threadIdx.x;
    if (idx < 8192) {
        int yv = idx >> 6, j = idx & 63, i = j & 31;
        float inv = powf(10000.0f, -(2.0f * (float)i) / 64.0f);
        float a = (float)yv * inv;
        d_tab[idx] = (j < 32) ? sinf(a) : cosf(a);
    } else if (idx < 16384) {
        int e = idx - 8192;
        int j = e >> 7, p = e & 127, i = j & 31;
        float inv = powf(10000.0f, -(2.0f * (float)i) / 64.0f);
        float a = (float)p * inv;
        d_tabT[e] = (j < 32) ? sinf(a) : cosf(a);
    } else if (idx < 16896) {
        int e = idx - 16384;
        int bin = e >> 6, j = e & 63, i = j & 31;
        float inv = powf(10000.0f, -(2.0f * (float)i) / 64.0f);
        float s = 0.0f;
        for (int t = 0; t < 16; ++t) {
            float a = (float)(bin * 16 + t) * inv;
            s += (j < 32) ? sinf(a) : cosf(a);
        }
        d_tabR[e] = s;
    } else if (idx < 33280) {
        int e = idx - 16896;
        d_pwT[e] = pw[(e & 127) * 128 + (e >> 7)];
    } else if (idx < 66048) {
        int e = idx - 33280;
        d_WkvT[e] = Wkv[(e & 255) * 128 + (e >> 8)];
    } else if (idx < 98816) {
        int i = idx - 66048;
        const float* W; unsigned char *H, *L; int e;
        if (i < 16384) { W = Wq; H = d_wqh; L = d_wql; e = i; }
        else           { W = Wp; H = d_wph; L = d_wpl; e = i - 16384; }
        int o = e >> 7, c = e & 127;
        float v = W[e];
        __nv_bfloat16 h = __float2bfloat16(v);
        float r = v - __bfloat162float(h);
        uint32_t off = (uint32_t)(o * TSTR + c * 2);
        *(__nv_bfloat16*)(H + off) = h;
        *(__nv_bfloat16*)(L + off) = __float2bfloat16(r);
    } else if (idx < 98816 + 52224) {
        ((uint32_t*)d_kth)[idx - 98816] = 0;
    } else if (idx < 98816 + 104448) {
        ((uint32_t*)d_ktl)[idx - 98816 - 52224] = 0;
    } else if (idx < 98816 + 104448 + 53248) {
        ((uint32_t*)d_vth)[idx - 98816 - 104448] = 0;
    } else if (idx < 98816 + 104448 + 106496) {
        ((uint32_t*)d_vtl)[idx - 98816 - 104448 - 53248] = 0;
    }
}

// ---------------- K1: ASPP pooling + depthwise conv (validated) -------------
__global__ void k_pool_dw(const float* __restrict__ x, const float* __restrict__ dw) {
    __shared__ float pm[64];
    __shared__ float g4[16];
    __shared__ float g2[4];
    __shared__ float g1[1];
    int tid = threadIdx.x;
    int b = blockIdx.x >> 7, c = blockIdx.x & 127;
    if (tid < 64) pm[tid] = 0.0f;
    __syncthreads();
    int r = tid >> 1, hf = tid & 1;
    const float4* xr = (const float4*)(x + ((size_t)(b * NC + c) << 14) + (r << 7) + (hf << 6));
    float sbin[4] = {0.0f, 0.0f, 0.0f, 0.0f};
#pragma unroll
    for (int q = 0; q < 16; ++q) {
        float4 v = xr[q];
        sbin[q >> 2] += (v.x + v.y) + (v.z + v.w);
    }
    int by = r >> 4;
#pragma unroll
    for (int t = 0; t < 4; ++t) atomicAdd(&pm[by * 8 + hf * 4 + t], sbin[t]);
    __syncthreads();
    if (tid < 64) {
        int byy = tid >> 3, bx = tid & 7;
        float pe = (c < 64) ? d_tabR[byy * 64 + c] : d_tabR[bx * 64 + (c - 64)];
        pm[tid] = (pm[tid] + 16.0f * pe) * (1.0f / 256.0f);
    }
    __syncthreads();
    if (tid < 16) {
        int i = tid >> 2, j = tid & 3;
        g4[tid] = 0.25f * (pm[(2 * i) * 8 + 2 * j] + pm[(2 * i) * 8 + 2 * j + 1] +
                           pm[(2 * i + 1) * 8 + 2 * j] + pm[(2 * i + 1) * 8 + 2 * j + 1]);
    } else if (tid < 20) {
        int t = tid - 16, i = t >> 1, j = t & 1;
        float s = 0.0f;
        for (int yy = 0; yy < 4; ++yy)
            for (int xq = 0; xq < 4; ++xq) s += pm[(4 * i + yy) * 8 + 4 * j + xq];
        g2[t] = s * (1.0f / 16.0f);
    } else if (tid == 20) {
        float s = 0.0f;
        for (int q = 0; q < 64; ++q) s += pm[q];
        g1[0] = s * (1.0f / 64.0f);
    }
    __syncthreads();
    if (tid < KVL) {
        float wv[9];
#pragma unroll
        for (int q = 0; q < 9; ++q) wv[q] = dw[c * 9 + q];
        const float* g; int s, ly, lx;
        if (tid < 64)      { g = pm; s = 8; ly = tid >> 3;        lx = tid & 7; }
        else if (tid < 80) { int t = tid - 64; g = g4; s = 4; ly = t >> 2; lx = t & 3; }
        else if (tid < 84) { int t = tid - 80; g = g2; s = 2; ly = t >> 1; lx = t & 1; }
        else               { g = g1; s = 1; ly = 0; lx = 0; }
        float a = 0.0f;
#pragma unroll
        for (int ky = 0; ky < 3; ++ky) {
            int iy = ly + ky - 1;
            bool oky = (iy >= 0) && (iy < s);
#pragma unroll
            for (int kx = 0; kx < 3; ++kx) {
                int ix = lx + kx - 1;
                if (oky && ix >= 0 && ix < s) a += g[iy * s + ix] * wv[ky * 3 + kx];
            }
        }
        d_y1[((size_t)b * KVL + tid) * NC + c] = a;
    }
}

// ---------------- K2: pointwise -> LN -> GELU -> KV proj (8-head tiles) -----
__global__ void k_pw_ln_kv(const float* __restrict__ lnw, const float* __restrict__ lnb) {
    __shared__ float ycol[128];
    __shared__ float part[256];
    __shared__ float zs[128];
    __shared__ float red[2];
    int tid = threadIdx.x;
    int b = blockIdx.x / KVL;
    int row = blockIdx.x - b * KVL;
    if (tid < 128) ycol[tid] = d_y1[((size_t)b * KVL + row) * NC + tid];
    __syncthreads();
    {
        int o = tid & 127, half = tid >> 7;
        const float* wc = d_pwT + (half << 6) * 128 + o;
        const float* yc = ycol + (half << 6);
        float a = 0.0f;
#pragma unroll 8
        for (int ci = 0; ci < 64; ++ci) a += wc[ci * 128] * yc[ci];
        part[tid] = a;
    }
    __syncthreads();
    if (tid < 128) zs[tid] = part[tid] + part[tid + 128];
    __syncthreads();
    if (tid < 32) {
        float s = zs[tid] + zs[tid + 32] + zs[tid + 64] + zs[tid + 96];
#pragma unroll
        for (int o = 16; o; o >>= 1) s += __shfl_xor_sync(0xffffffffu, s, o);
        if (tid == 0) red[0] = s * (1.0f / 128.0f);
    }
    __syncthreads();
    float mu = red[0];
    if (tid < 32) {
        float s = 0.0f;
#pragma unroll
        for (int q = 0; q < 4; ++q) { float dd = zs[tid + 32 * q] - mu; s += dd * dd; }
#pragma unroll
        for (int o = 16; o; o >>= 1) s += __shfl_xor_sync(0xffffffffu, s, o);
        if (tid == 0) red[1] = s * (1.0f / 128.0f);
    }
    __syncthreads();
    float rstd = rsqrtf(red[1] + 1e-5f);
    if (tid < 128) {
        float zn = (zs[tid] - mu) * rstd * lnw[tid] + lnb[tid];
        zs[tid] = 0.5f * zn * (1.0f + erff(zn * 0.70710678118654752f));
    }
    __syncthreads();
    float a = 0.0f;
    const float* wc = d_WkvT + tid;
#pragma unroll 8
    for (int ci = 0; ci < 128; ++ci) a += wc[ci * 256] * zs[ci];
    __nv_bfloat16 h = __float2bfloat16(a);
    __nv_bfloat16 l = __float2bfloat16(a - __bfloat162float(h));
    if (tid < 128) {
        int m = tid >> 4, d = tid & 15;
        uint32_t off = ((uint32_t)b * 96 + row) * K8STR + m * 32 + d * 2;
        *(__nv_bfloat16*)(d_kth + off) = h;
        *(__nv_bfloat16*)(d_ktl + off) = l;
    } else {
        int cc = tid - 128;
        int m = cc >> 4, d = cc & 15;
        uint32_t off = ((uint32_t)b * 128 + m * 16 + d) * V8STR + row * 2;
        *(__nv_bfloat16*)(d_vth + off) = h;
        *(__nv_bfloat16*)(d_vtl + off) = l;
    }
}

// ---------------- K3: fused main — M=2 attention tasks, 1024 threads --------
#define OXH 0
#define OXL TILEB              // R1: X -> Q -> O (hi at OXH, lo at OXL)
#define OW  (2 * TILEB)        // R2: Wq/Wproj (hi, lo at +TILEB); KV overlays
#define OK8H OW
#define OK8L (OK8H + K8TILE)
#define OV8H (OK8L + K8TILE)
#define OV8L (OV8H + V8TILE)
#define OBI  (OV8L + V8TILE)
#define SMB  (OBI + 512 + 64)

#define LDMX4(r0, r1, r2, r3, a) \
    asm volatile("ldmatrix.sync.aligned.m8n8.x4.shared.b16 {%0,%1,%2,%3}, [%4];" \
        : "=r"(r0), "=r"(r1), "=r"(r2), "=r"(r3) : "r"(a))
#define LDMX2(r0, r1, a) \
    asm volatile("ldmatrix.sync.aligned.m8n8.x2.shared.b16 {%0,%1}, [%2];" \
        : "=r"(r0), "=r"(r1) : "r"(a))
#define MMA16816(d, a0, a1, a2, a3, b0, b1) \
    asm volatile("mma.sync.aligned.m16n8k16.row.col.f32.bf16.bf16.f32 " \
        "{%0,%1,%2,%3}, {%4,%5,%6,%7}, {%8,%9}, {%0,%1,%2,%3};" \
        : "+f"((d)[0]), "+f"((d)[1]), "+f"((d)[2]), "+f"((d)[3]) \
        : "r"(a0), "r"(a1), "r"(a2), "r"(a3), "r"(b0), "r"(b1))

// D[m=A-rows][n=B-rows]: 32 warps, mt=w&7 (16 A-rows), nq=w>>3 (32 B-rows)
__device__ __forceinline__ void hmma_gemm(uint32_t sb, uint32_t aBase, uint32_t bBase,
                                          int w, int lane, float D[4][4]) {
#pragma unroll
    for (int n = 0; n < 4; ++n)
#pragma unroll
        for (int q = 0; q < 4; ++q) D[n][q] = 0.0f;
    int mt = w & 7, nq = w >> 3;
    int sub = lane >> 3, r = lane & 7;
    uint32_t aH = sb + aBase + (uint32_t)((mt * 16 + (sub & 1) * 8 + r) * TSTR + (sub >> 1) * 16);
    uint32_t aL = aH + TILEB;
    int bl = lane & 15;
    uint32_t bH = sb + bBase + (uint32_t)((nq * 32 + (bl & 7)) * TSTR + (bl >> 3) * 16);
    uint32_t bL = bH + TILEB;
#pragma unroll
    for (int kc = 0; kc < 8; ++kc) {
        uint32_t ah0, ah1, ah2, ah3, al0, al1, al2, al3;
        LDMX4(ah0, ah1, ah2, ah3, aH + kc * 32);
        LDMX4(al0, al1, al2, al3, aL + kc * 32);
#pragma unroll
        for (int n = 0; n < 4; ++n) {
            uint32_t bh0, bh1, bl0, bl1;
            LDMX2(bh0, bh1, bH + n * (8 * TSTR) + kc * 32);
            LDMX2(bl0, bl1, bL + n * (8 * TSTR) + kc * 32);
            MMA16816(D[n], ah0, ah1, ah2, ah3, bh0, bh1);
            MMA16816(D[n], al0, al1, al2, al3, bh0, bh1);
            MMA16816(D[n], ah0, ah1, ah2, ah3, bl0, bl1);
        }
    }
}

__global__ void __launch_bounds__(1024, 1)
k_main(const float* __restrict__ x, const float* __restrict__ bproj,
       float* __restrict__ out) {
    extern __shared__ char smc[];
    uint32_t sb;
    asm("{ .reg .u64 t; cvta.to.shared.u64 t, %1; cvt.u32.u64 %0, t; }" : "=r"(sb) : "l"(smc));
    int tid = threadIdx.x, w = tid >> 5, lane = tid & 31;
    int b = blockIdx.x >> 7, y = blockIdx.x & 127;

    if (tid < 128) ((float*)(smc + OBI))[tid] = bproj[tid];
    {   // Wq tiles -> R2
        const float4* h4 = (const float4*)d_wqh;
        const float4* l4 = (const float4*)d_wql;
        float4* wh = (float4*)(smc + OW);
        float4* wl = (float4*)(smc + OW + TILEB);
        for (int i = tid; i < TILEB / 16; i += 1024) { wh[i] = h4[i]; wl[i] = l4[i]; }
    }
    {   // Xp bf16 split tiles -> R1: rows=px, cols=c
        int p = tid & 127;
        int yoff = y << 7;
        for (int g = tid >> 7; g < 64; g += 8) {
            int c0 = g * 2, c1 = c0 + 1;
            float v0 = x[((size_t)(b * NC + c0) << 14) + yoff + p];
            float v1 = x[((size_t)(b * NC + c1) << 14) + yoff + p];
            v0 += (c0 < 64) ? d_tab[y * 64 + c0] : d_tabT[(c0 - 64) * 128 + p];
            v1 += (c1 < 64) ? d_tab[y * 64 + c1] : d_tabT[(c1 - 64) * 128 + p];
            uint32_t hi, lo;
            bfsplit(v0, v1, hi, lo);
            uint32_t off = (uint32_t)(p * TSTR + c0 * 2);
            *(uint32_t*)(smc + OXH + off) = hi;
            *(uint32_t*)(smc + OXL + off) = lo;
        }
    }
    __syncthreads();

    float D[4][4];
    // ---- Q-GEMM: D[px][c] (A = X, B = Wq) ----
    hmma_gemm(sb, OXH, OW, w, lane, D);
    __syncthreads();   // X and Wq reads done; R1 and R2 free

    int q = lane & 3, rr = lane >> 2;
    {   // stage Q (x0.25, bf16 hi/lo) into R1 (overwrites X)
        int mt = w & 7, nq = w >> 3;
        int px0 = mt * 16 + rr;
#pragma unroll
        for (int n = 0; n < 4; ++n) {
            int c = nq * 32 + n * 8 + q * 2;
            uint32_t hi, lo;
            bfsplit(D[n][0] * 0.25f, D[n][1] * 0.25f, hi, lo);
            *(uint32_t*)(smc + OXH + px0 * TSTR + c * 2) = hi;
            *(uint32_t*)(smc + OXL + px0 * TSTR + c * 2) = lo;
            bfsplit(D[n][2] * 0.25f, D[n][3] * 0.25f, hi, lo);
            *(uint32_t*)(smc + OXH + (px0 + 8) * TSTR + c * 2) = hi;
            *(uint32_t*)(smc + OXL + (px0 + 8) * TSTR + c * 2) = lo;
        }
    }
    {   // fill K/V (all 8 heads) into R2
        const float4* kh = (const float4*)(d_kth + (size_t)b * K8TILE);
        const float4* kl = (const float4*)(d_ktl + (size_t)b * K8TILE);
        const float4* vh = (const float4*)(d_vth + (size_t)b * V8TILE);
        const float4* vl = (const float4*)(d_vtl + (size_t)b * V8TILE);
        float4* dkh = (float4*)(smc + OK8H);
        float4* dkl = (float4*)(smc + OK8L);
        float4* dvh = (float4*)(smc + OV8H);
        float4* dvl = (float4*)(smc + OV8L);
        for (int i = tid; i < K8TILE / 16; i += 1024) { dkh[i] = kh[i]; dkl[i] = kl[i]; }
        for (int i = tid; i < V8TILE / 16; i += 1024) { dvh[i] = vh[i]; dvl[i] = vl[i]; }
    }
    __syncthreads();

    // ---- attention: one task/warp = (head h = w&7, 32-px group pg = w>>3) ----
    int h = w & 7, pg = w >> 3;
    int sub = lane >> 3, r8 = lane & 7, bl = lane & 15;
    uint32_t qh[2][4], ql[2][4];
#pragma unroll
    for (int m = 0; m < 2; ++m) {
        uint32_t qa = sb + OXH + (uint32_t)((pg * 32 + m * 16 + (sub & 1) * 8 + r8) * TSTR
                    + h * 32 + (sub >> 1) * 16);
        LDMX4(qh[m][0], qh[m][1], qh[m][2], qh[m][3], qa);
        LDMX4(ql[m][0], ql[m][1], ql[m][2], ql[m][3], qa + TILEB);
    }
    __syncthreads();   // all Q frags loaded before O overwrites R1

    uint32_t kbase = sb + OK8H + (uint32_t)((bl & 7) * K8STR + h * 32 + (bl >> 3) * 16);
    uint32_t vbase = sb + OV8H + (uint32_t)((h * 16 + (bl & 7)) * V8STR + (bl >> 3) * 16);
    float o[2][2][4];
#pragma unroll
    for (int m = 0; m < 2; ++m)
#pragma unroll
        for (int n = 0; n < 2; ++n)
#pragma unroll
            for (int e = 0; e < 4; ++e) o[m][n][e] = 0.0f;
    float sr[2] = {0.0f, 0.0f}, sr8[2] = {0.0f, 0.0f};
#pragma unroll
    for (int ks = 0; ks < 6; ++ks) {
        float P[2][2][4];
#pragma unroll
        for (int jt = 0; jt < 2; ++jt) {
            uint32_t kh0, kh1, kl0, kl1;
            LDMX2(kh0, kh1, kbase + (2 * ks + jt) * (8 * K8STR));
            LDMX2(kl0, kl1, kbase + (2 * ks + jt) * (8 * K8STR) + K8TILE);
#pragma unroll
            for (int m = 0; m < 2; ++m) {
                P[m][jt][0] = 0.0f; P[m][jt][1] = 0.0f;
                P[m][jt][2] = 0.0f; P[m][jt][3] = 0.0f;
                MMA16816(P[m][jt], qh[m][0], qh[m][1], qh[m][2], qh[m][3], kh0, kh1);
                MMA16816(P[m][jt], ql[m][0], ql[m][1], ql[m][2], ql[m][3], kh0, kh1);
                MMA16816(P[m][jt], qh[m][0], qh[m][1], qh[m][2], qh[m][3], kl0, kl1);
            }
        }
        uint32_t pah[2][4], pal[2][4];
#pragma unroll
        for (int m = 0; m < 2; ++m) {
            float e00 = __expf(P[m][0][0]), e01 = __expf(P[m][0][1]);
            float e02 = __expf(P[m][0][2]), e03 = __expf(P[m][0][3]);
            float e10 = __expf(P[m][1][0]), e11 = __expf(P[m][1][1]);
            float e12 = __expf(P[m][1][2]), e13 = __expf(P[m][1][3]);
            sr[m] += (e00 + e01) + (e10 + e11);
            sr8[m] += (e02 + e03) + (e12 + e13);
            bfsplit(e00, e01, pah[m][0], pal[m][0]);
            bfsplit(e02, e03, pah[m][1], pal[m][1]);
            bfsplit(e10, e11, pah[m][2], pal[m][2]);
            bfsplit(e12, e13, pah[m][3], pal[m][3]);
        }
#pragma unroll
        for (int n = 0; n < 2; ++n) {
            uint32_t vh0, vh1, vl0, vl1;
            LDMX2(vh0, vh1, vbase + n * (8 * V8STR) + ks * 32);
            LDMX2(vl0, vl1, vbase + n * (8 * V8STR) + ks * 32 + V8TILE);
#pragma unroll
            for (int m = 0; m < 2; ++m) {
                MMA16816(o[m][n], pah[m][0], pah[m][1], pah[m][2], pah[m][3], vh0, vh1);
                MMA16816(o[m][n], pal[m][0], pal[m][1], pal[m][2], pal[m][3], vh0, vh1);
                MMA16816(o[m][n], pah[m][0], pah[m][1], pah[m][2], pah[m][3], vl0, vl1);
            }
        }
    }
#pragma unroll
    for (int m = 0; m < 2; ++m) {
        float s = sr[m], s8 = sr8[m];
        s += __shfl_xor_sync(0xffffffffu, s, 1);
        s += __shfl_xor_sync(0xffffffffu, s, 2);
        s8 += __shfl_xor_sync(0xffffffffu, s8, 1);
        s8 += __shfl_xor_sync(0xffffffffu, s8, 2);
        float ir = 1.0f / (s - 11.0f), ir8 = 1.0f / (s8 - 11.0f);
        int px0 = pg * 32 + m * 16 + rr;
#pragma unroll
        for (int n = 0; n < 2; ++n) {
            int c0 = h * 16 + n * 8 + q * 2;
            uint32_t hi, lo;
            bfsplit(o[m][n][0] * ir, o[m][n][1] * ir, hi, lo);
            *(uint32_t*)(smc + OXH + px0 * TSTR + c0 * 2) = hi;
            *(uint32_t*)(smc + OXL + px0 * TSTR + c0 * 2) = lo;
            bfsplit(o[m][n][2] * ir8, o[m][n][3] * ir8, hi, lo);
            *(uint32_t*)(smc + OXH + (px0 + 8) * TSTR + c0 * 2) = hi;
            *(uint32_t*)(smc + OXL + (px0 + 8) * TSTR + c0 * 2) = lo;
        }
    }
    __syncthreads();   // O complete; KV dead
    {   // Wproj tiles -> R2
        const float4* h4 = (const float4*)d_wph;
        const float4* l4 = (const float4*)d_wpl;
        float4* wh = (float4*)(smc + OW);
        float4* wl = (float4*)(smc + OW + TILEB);
        for (int i = tid; i < TILEB / 16; i += 1024) { wh[i] = h4[i]; wl[i] = l4[i]; }
    }
    __syncthreads();

    // ---- out-proj GEMM: D[px][c] (A = O, B = Wproj) + bias + store ----
    hmma_gemm(sb, OXH, OW, w, lane, D);
    {
        const float* bias = (const float*)(smc + OBI);
        int mt = w & 7, nq = w >> 3;
        int px0 = mt * 16 + rr;
        float* og = out + (((size_t)b * NC) << 14) + (y << 7);
#pragma unroll
        for (int n = 0; n < 4; ++n) {
            int c0 = nq * 32 + n * 8 + q * 2;
            float b0 = bias[c0], b1 = bias[c0 + 1];
            float* p0 = og + (((size_t)c0) << 14);
            float* p1 = og + (((size_t)(c0 + 1)) << 14);
            p0[px0] = D[n][0] + b0;
            p1[px0] = D[n][1] + b1;
            p0[px0 + 8] = D[n][2] + b0;
            p1[px0 + 8] = D[n][3] + b1;
        }
    }
}

// ----------------------------------------------------------------------------
extern "C" void kernel_launch(void* const* d_in, const int* in_sizes, int n_in,
                              void* d_out, int out_size) {
    const float* x     = (const float*)d_in[0];
    const float* Wq    = (const float*)d_in[1];
    const float* Wkv   = (const float*)d_in[2];
    const float* Wproj = (const float*)d_in[3];
    const float* bproj = (const float*)d_in[4];
    const float* dw    = (const float*)d_in[5];
    const float* pw    = (const float*)d_in[6];
    const float* lnw   = (const float*)d_in[7];
    const float* lnb   = (const float*)d_in[8];
    float* out = (float*)d_out;

    cudaFuncSetAttribute(k_main, cudaFuncAttributeMaxDynamicSharedMemorySize, SMB);

    k_prep<<<1210, 256>>>(pw, Wkv, Wq, Wproj);
    k_pool_dw<<<NB * NC, 256>>>(x, dw);
    k_pw_ln_kv<<<NB * KVL, 256>>>(lnw, lnb);
    k_main<<<NB * 128, 1024, SMB>>>(x, bproj, out);
}

// round 16
// speedup vs baseline: 1.1898x; 1.1632x over previous
#include <cuda_runtime.h>
#include <cuda_bf16.h>
#include <math.h>
#include <stdint.h>

#define NB 8
#define NC 128
#define NH 8
#define HD 16
#define KVL 85

#define TSTR 272
#define TILEB (128 * TSTR)     // 34816
#define K8STR 272
#define K8TILE (96 * K8STR)    // 26112: rows=kv(96 pad), cols=8 heads x 16c
#define V8STR 208
#define V8TILE (128 * V8STR)   // 26624: rows=8 heads x 16c, cols=j(96 pad 104)

__device__ __align__(16) float d_tab[128 * 64];
__device__ __align__(16) float d_tabT[64 * 128];
__device__ __align__(16) float d_tabR[8 * 64];
__device__ __align__(16) float d_y1[NB * KVL * NC];
__device__ __align__(16) float d_pwT[128 * 128];
__device__ __align__(16) float d_WkvT[128 * 256];
__device__ __align__(16) float d_vsum[NB * 128];     // exact fp32 per-head V colsum
__device__ __align__(16) unsigned char d_wqh[TILEB];
__device__ __align__(16) unsigned char d_wql[TILEB];
__device__ __align__(16) unsigned char d_wph[TILEB];
__device__ __align__(16) unsigned char d_wpl[TILEB];
__device__ __align__(16) unsigned char d_kth[NB * K8TILE];
__device__ __align__(16) unsigned char d_vth[NB * V8TILE];

__device__ __forceinline__ uint32_t bf2u(__nv_bfloat162 v) {
    return ((uint32_t)__bfloat16_as_ushort(v.y) << 16) | (uint32_t)__bfloat16_as_ushort(v.x);
}
__device__ __forceinline__ void bfsplit(float v0, float v1, uint32_t& hi, uint32_t& lo) {
    __nv_bfloat162 hh = __floats2bfloat162_rn(v0, v1);
    __nv_bfloat162 ll = __floats2bfloat162_rn(v0 - __bfloat162float(hh.x),
                                              v1 - __bfloat162float(hh.y));
    hi = bf2u(hh); lo = bf2u(ll);
}

// ---------------- K0: tables + transposes + weight split + zeroing ----------
__global__ void k_prep(const float* __restrict__ pw, const float* __restrict__ Wkv,
                       const float* __restrict__ Wq, const float* __restrict__ Wp) {
    int idx = blockIdx.x * 256 + threadIdx.x;
    if (idx < 8192) {
        int yv = idx >> 6, j = idx & 63, i = j & 31;
        float inv = powf(10000.0f, -(2.0f * (float)i) / 64.0f);
        float a = (float)yv * inv;
        d_tab[idx] = (j < 32) ? sinf(a) : cosf(a);
    } else if (idx < 16384) {
        int e = idx - 8192;
        int j = e >> 7, p = e & 127, i = j & 31;
        float inv = powf(10000.0f, -(2.0f * (float)i) / 64.0f);
        float a = (float)p * inv;
        d_tabT[e] = (j < 32) ? sinf(a) : cosf(a);
    } else if (idx < 16896) {
        int e = idx - 16384;
        int bin = e >> 6, j = e & 63, i = j & 31;
        float inv = powf(10000.0f, -(2.0f * (float)i) / 64.0f);
        float s = 0.0f;
        for (int t = 0; t < 16; ++t) {
            float a = (float)(bin * 16 + t) * inv;
            s += (j < 32) ? sinf(a) : cosf(a);
        }
        d_tabR[e] = s;
    } else if (idx < 33280) {
        int e = idx - 16896;
        d_pwT[e] = pw[(e & 127) * 128 + (e >> 7)];
    } else if (idx < 66048) {
        int e = idx - 33280;
        d_WkvT[e] = Wkv[(e & 255) * 128 + (e >> 8)];
    } else if (idx < 98816) {
        int i = idx - 66048;
        const float* W; unsigned char *H, *L; int e;
        if (i < 16384) { W = Wq; H = d_wqh; L = d_wql; e = i; }
        else           { W = Wp; H = d_wph; L = d_wpl; e = i - 16384; }
        int o = e >> 7, c = e & 127;
        float v = W[e];
        __nv_bfloat16 h = __float2bfloat16(v);
        float r = v - __bfloat162float(h);
        uint32_t off = (uint32_t)(o * TSTR + c * 2);
        *(__nv_bfloat16*)(H + off) = h;
        *(__nv_bfloat16*)(L + off) = __float2bfloat16(r);
    } else if (idx < 98816 + 52224) {
        ((uint32_t*)d_kth)[idx - 98816] = 0;
    } else if (idx < 98816 + 52224 + 53248) {
        ((uint32_t*)d_vth)[idx - 98816 - 52224] = 0;
    } else if (idx < 98816 + 52224 + 53248 + 1024) {
        d_vsum[idx - 98816 - 52224 - 53248] = 0.0f;
    }
}

// ---------------- K1: ASPP pooling + depthwise conv (validated) -------------
__global__ void k_pool_dw(const float* __restrict__ x, const float* __restrict__ dw) {
    __shared__ float pm[64];
    __shared__ float g4[16];
    __shared__ float g2[4];
    __shared__ float g1[1];
    int tid = threadIdx.x;
    int b = blockIdx.x >> 7, c = blockIdx.x & 127;
    if (tid < 64) pm[tid] = 0.0f;
    __syncthreads();
    int r = tid >> 1, hf = tid & 1;
    const float4* xr = (const float4*)(x + ((size_t)(b * NC + c) << 14) + (r << 7) + (hf << 6));
    float sbin[4] = {0.0f, 0.0f, 0.0f, 0.0f};
#pragma unroll
    for (int q = 0; q < 16; ++q) {
        float4 v = xr[q];
        sbin[q >> 2] += (v.x + v.y) + (v.z + v.w);
    }
    int by = r >> 4;
#pragma unroll
    for (int t = 0; t < 4; ++t) atomicAdd(&pm[by * 8 + hf * 4 + t], sbin[t]);
    __syncthreads();
    if (tid < 64) {
        int byy = tid >> 3, bx = tid & 7;
        float pe = (c < 64) ? d_tabR[byy * 64 + c] : d_tabR[bx * 64 + (c - 64)];
        pm[tid] = (pm[tid] + 16.0f * pe) * (1.0f / 256.0f);
    }
    __syncthreads();
    if (tid < 16) {
        int i = tid >> 2, j = tid & 3;
        g4[tid] = 0.25f * (pm[(2 * i) * 8 + 2 * j] + pm[(2 * i) * 8 + 2 * j + 1] +
                           pm[(2 * i + 1) * 8 + 2 * j] + pm[(2 * i + 1) * 8 + 2 * j + 1]);
    } else if (tid < 20) {
        int t = tid - 16, i = t >> 1, j = t & 1;
        float s = 0.0f;
        for (int yy = 0; yy < 4; ++yy)
            for (int xq = 0; xq < 4; ++xq) s += pm[(4 * i + yy) * 8 + 4 * j + xq];
        g2[t] = s * (1.0f / 16.0f);
    } else if (tid == 20) {
        float s = 0.0f;
        for (int q = 0; q < 64; ++q) s += pm[q];
        g1[0] = s * (1.0f / 64.0f);
    }
    __syncthreads();
    if (tid < KVL) {
        float wv[9];
#pragma unroll
        for (int q = 0; q < 9; ++q) wv[q] = dw[c * 9 + q];
        const float* g; int s, ly, lx;
        if (tid < 64)      { g = pm; s = 8; ly = tid >> 3;        lx = tid & 7; }
        else if (tid < 80) { int t = tid - 64; g = g4; s = 4; ly = t >> 2; lx = t & 3; }
        else if (tid < 84) { int t = tid - 80; g = g2; s = 2; ly = t >> 1; lx = t & 1; }
        else               { g = g1; s = 1; ly = 0; lx = 0; }
        float a = 0.0f;
#pragma unroll
        for (int ky = 0; ky < 3; ++ky) {
            int iy = ly + ky - 1;
            bool oky = (iy >= 0) && (iy < s);
#pragma unroll
            for (int kx = 0; kx < 3; ++kx) {
                int ix = lx + kx - 1;
                if (oky && ix >= 0 && ix < s) a += g[iy * s + ix] * wv[ky * 3 + kx];
            }
        }
        d_y1[((size_t)b * KVL + tid) * NC + c] = a;
    }
}

// ---------------- K2: pointwise -> LN -> GELU -> KV proj + V colsum ---------
__global__ void k_pw_ln_kv(const float* __restrict__ lnw, const float* __restrict__ lnb) {
    __shared__ float ycol[128];
    __shared__ float part[256];
    __shared__ float zs[128];
    __shared__ float red[2];
    int tid = threadIdx.x;
    int b = blockIdx.x / KVL;
    int row = blockIdx.x - b * KVL;
    if (tid < 128) ycol[tid] = d_y1[((size_t)b * KVL + row) * NC + tid];
    __syncthreads();
    {
        int o = tid & 127, half = tid >> 7;
        const float* wc = d_pwT + (half << 6) * 128 + o;
        const float* yc = ycol + (half << 6);
        float a = 0.0f;
#pragma unroll 8
        for (int ci = 0; ci < 64; ++ci) a += wc[ci * 128] * yc[ci];
        part[tid] = a;
    }
    __syncthreads();
    if (tid < 128) zs[tid] = part[tid] + part[tid + 128];
    __syncthreads();
    if (tid < 32) {
        float s = zs[tid] + zs[tid + 32] + zs[tid + 64] + zs[tid + 96];
#pragma unroll
        for (int o = 16; o; o >>= 1) s += __shfl_xor_sync(0xffffffffu, s, o);
        if (tid == 0) red[0] = s * (1.0f / 128.0f);
    }
    __syncthreads();
    float mu = red[0];
    if (tid < 32) {
        float s = 0.0f;
#pragma unroll
        for (int q = 0; q < 4; ++q) { float dd = zs[tid + 32 * q] - mu; s += dd * dd; }
#pragma unroll
        for (int o = 16; o; o >>= 1) s += __shfl_xor_sync(0xffffffffu, s, o);
        if (tid == 0) red[1] = s * (1.0f / 128.0f);
    }
    __syncthreads();
    float rstd = rsqrtf(red[1] + 1e-5f);
    if (tid < 128) {
        float zn = (zs[tid] - mu) * rstd * lnw[tid] + lnb[tid];
        zs[tid] = 0.5f * zn * (1.0f + erff(zn * 0.70710678118654752f));
    }
    __syncthreads();
    float a = 0.0f;
    const float* wc = d_WkvT + tid;
#pragma unroll 8
    for (int ci = 0; ci < 128; ++ci) a += wc[ci * 256] * zs[ci];
    __nv_bfloat16 h = __float2bfloat16(a);
    if (tid < 128) {       // K: hi only (2-chain QK), rows=kv j, cols=head*16+d
        int m = tid >> 4, d = tid & 15;
        uint32_t off = ((uint32_t)b * 96 + row) * K8STR + m * 32 + d * 2;
        *(__nv_bfloat16*)(d_kth + off) = h;
    } else {               // V^T hi + exact fp32 colsum
        int cc = tid - 128;
        int m = cc >> 4, d = cc & 15;
        uint32_t off = ((uint32_t)b * 128 + m * 16 + d) * V8STR + row * 2;
        *(__nv_bfloat16*)(d_vth + off) = h;
        atomicAdd(&d_vsum[b * 128 + cc], a);
    }
}

// ---------------- K3: fused main — reduced-chain HMMA, 1024 threads ---------
#define OXH 0
#define OXL TILEB              // R1: X -> Q -> O (hi, lo)
#define OW  (2 * TILEB)        // R2: Wq-hi / KV-hi / Wproj hi+lo
#define OK8H OW
#define OV8H (OK8H + K8TILE)
#define OBI  (OW + 2 * TILEB)  // 139264
#define OVS  (OBI + 512)
#define SMB  (OVS + 512 + 64)

#define LDMX4(r0, r1, r2, r3, a) \
    asm volatile("ldmatrix.sync.aligned.m8n8.x4.shared.b16 {%0,%1,%2,%3}, [%4];" \
        : "=r"(r0), "=r"(r1), "=r"(r2), "=r"(r3) : "r"(a))
#define LDMX2(r0, r1, a) \
    asm volatile("ldmatrix.sync.aligned.m8n8.x2.shared.b16 {%0,%1}, [%2];" \
        : "=r"(r0), "=r"(r1) : "r"(a))
#define MMA16816(d, a0, a1, a2, a3, b0, b1) \
    asm volatile("mma.sync.aligned.m16n8k16.row.col.f32.bf16.bf16.f32 " \
        "{%0,%1,%2,%3}, {%4,%5,%6,%7}, {%8,%9}, {%0,%1,%2,%3};" \
        : "+f"((d)[0]), "+f"((d)[1]), "+f"((d)[2]), "+f"((d)[3]) \
        : "r"(a0), "r"(a1), "r"(a2), "r"(a3), "r"(b0), "r"(b1))

// D[m=A-rows][n=B-rows]: 32 warps, mt=w&7 (16 A-rows), nq=w>>3 (32 B-rows)
// FULL: 3-chain (AhBh + AlBh + AhBl). !FULL: 2-chain (B-lo never loaded).
template <bool FULL>
__device__ __forceinline__ void hmma_gemm(uint32_t sb, uint32_t aBase, uint32_t bBase,
                                          int w, int lane, float D[4][4]) {
#pragma unroll
    for (int n = 0; n < 4; ++n)
#pragma unroll
        for (int q = 0; q < 4; ++q) D[n][q] = 0.0f;
    int mt = w & 7, nq = w >> 3;
    int sub = lane >> 3, r = lane & 7;
    uint32_t aH = sb + aBase + (uint32_t)((mt * 16 + (sub & 1) * 8 + r) * TSTR + (sub >> 1) * 16);
    uint32_t aL = aH + TILEB;
    int bl = lane & 15;
    uint32_t bH = sb + bBase + (uint32_t)((nq * 32 + (bl & 7)) * TSTR + (bl >> 3) * 16);
#pragma unroll
    for (int kc = 0; kc < 8; ++kc) {
        uint32_t ah0, ah1, ah2, ah3, al0, al1, al2, al3;
        LDMX4(ah0, ah1, ah2, ah3, aH + kc * 32);
        LDMX4(al0, al1, al2, al3, aL + kc * 32);
#pragma unroll
        for (int n = 0; n < 4; ++n) {
            uint32_t bh0, bh1;
            LDMX2(bh0, bh1, bH + n * (8 * TSTR) + kc * 32);
            MMA16816(D[n], ah0, ah1, ah2, ah3, bh0, bh1);
            MMA16816(D[n], al0, al1, al2, al3, bh0, bh1);
            if (FULL) {
                uint32_t bl0, bl1;
                LDMX2(bl0, bl1, bH + TILEB + n * (8 * TSTR) + kc * 32);
                MMA16816(D[n], ah0, ah1, ah2, ah3, bl0, bl1);
            }
        }
    }
}

__global__ void __launch_bounds__(1024, 1)
k_main(const float* __restrict__ x, const float* __restrict__ bproj,
       float* __restrict__ out) {
    extern __shared__ char smc[];
    uint32_t sb;
    asm("{ .reg .u64 t; cvta.to.shared.u64 t, %1; cvt.u32.u64 %0, t; }" : "=r"(sb) : "l"(smc));
    int tid = threadIdx.x, w = tid >> 5, lane = tid & 31;
    int b = blockIdx.x >> 7, y = blockIdx.x & 127;

    if (tid < 128) ((float*)(smc + OBI))[tid] = bproj[tid];
    else if (tid < 256) ((float*)(smc + OVS))[tid - 128] = d_vsum[b * 128 + tid - 128];
    {   // Wq tile (hi only) -> R2
        const float4* h4 = (const float4*)d_wqh;
        float4* wh = (float4*)(smc + OW);
        for (int i = tid; i < TILEB / 16; i += 1024) wh[i] = h4[i];
    }
    {   // Xp bf16 split tiles -> R1: rows=px, cols=c
        int p = tid & 127;
        int yoff = y << 7;
        for (int g = tid >> 7; g < 64; g += 8) {
            int c0 = g * 2, c1 = c0 + 1;
            float v0 = x[((size_t)(b * NC + c0) << 14) + yoff + p];
            float v1 = x[((size_t)(b * NC + c1) << 14) + yoff + p];
            v0 += (c0 < 64) ? d_tab[y * 64 + c0] : d_tabT[(c0 - 64) * 128 + p];
            v1 += (c1 < 64) ? d_tab[y * 64 + c1] : d_tabT[(c1 - 64) * 128 + p];
            uint32_t hi, lo;
            bfsplit(v0, v1, hi, lo);
            uint32_t off = (uint32_t)(p * TSTR + c0 * 2);
            *(uint32_t*)(smc + OXH + off) = hi;
            *(uint32_t*)(smc + OXL + off) = lo;
        }
    }
    __syncthreads();

    float D[4][4];
    // ---- Q-GEMM (2-chain): D[px][c] (A = X hi/lo, B = Wq hi) ----
    hmma_gemm<false>(sb, OXH, OW, w, lane, D);
    __syncthreads();   // X and Wq reads done; R1 and R2 free

    int q = lane & 3, rr = lane >> 2;
    {   // stage Q (x0.25, bf16 hi/lo) into R1 (overwrites X)
        int mt = w & 7, nq = w >> 3;
        int px0 = mt * 16 + rr;
#pragma unroll
        for (int n = 0; n < 4; ++n) {
            int c = nq * 32 + n * 8 + q * 2;
            uint32_t hi, lo;
            bfsplit(D[n][0] * 0.25f, D[n][1] * 0.25f, hi, lo);
            *(uint32_t*)(smc + OXH + px0 * TSTR + c * 2) = hi;
            *(uint32_t*)(smc + OXL + px0 * TSTR + c * 2) = lo;
            bfsplit(D[n][2] * 0.25f, D[n][3] * 0.25f, hi, lo);
            *(uint32_t*)(smc + OXH + (px0 + 8) * TSTR + c * 2) = hi;
            *(uint32_t*)(smc + OXL + (px0 + 8) * TSTR + c * 2) = lo;
        }
    }
    {   // fill K-hi / V-hi (all 8 heads) into R2
        const float4* kh = (const float4*)(d_kth + (size_t)b * K8TILE);
        const float4* vh = (const float4*)(d_vth + (size_t)b * V8TILE);
        float4* dkh = (float4*)(smc + OK8H);
        float4* dvh = (float4*)(smc + OV8H);
        for (int i = tid; i < K8TILE / 16; i += 1024) dkh[i] = kh[i];
        for (int i = tid; i < V8TILE / 16; i += 1024) dvh[i] = vh[i];
    }
    __syncthreads();

    // ---- attention: one task/warp = (head h = w&7, 32-px group pg = w>>3) ----
    int h = w & 7, pg = w >> 3;
    int sub = lane >> 3, r8 = lane & 7, bl = lane & 15;
    uint32_t qh[2][4], ql[2][4];
#pragma unroll
    for (int m = 0; m < 2; ++m) {
        uint32_t qa = sb + OXH + (uint32_t)((pg * 32 + m * 16 + (sub & 1) * 8 + r8) * TSTR
                    + h * 32 + (sub >> 1) * 16);
        LDMX4(qh[m][0], qh[m][1], qh[m][2], qh[m][3], qa);
        LDMX4(ql[m][0], ql[m][1], ql[m][2], ql[m][3], qa + TILEB);
    }
    __syncthreads();   // all Q frags loaded before O overwrites R1

    uint32_t kbase = sb + OK8H + (uint32_t)((bl & 7) * K8STR + h * 32 + (bl >> 3) * 16);
    uint32_t vbase = sb + OV8H + (uint32_t)((h * 16 + (bl & 7)) * V8STR + (bl >> 3) * 16);
    float o[2][2][4];
#pragma unroll
    for (int m = 0; m < 2; ++m)
#pragma unroll
        for (int n = 0; n < 2; ++n)
#pragma unroll
            for (int e = 0; e < 4; ++e) o[m][n][e] = 0.0f;
    float sr[2] = {0.0f, 0.0f}, sr8[2] = {0.0f, 0.0f};
#pragma unroll
    for (int ks = 0; ks < 6; ++ks) {
        float P[2][2][4];
#pragma unroll
        for (int jt = 0; jt < 2; ++jt) {
            uint32_t kh0, kh1;
            LDMX2(kh0, kh1, kbase + (2 * ks + jt) * (8 * K8STR));
#pragma unroll
            for (int m = 0; m < 2; ++m) {
                P[m][jt][0] = 0.0f; P[m][jt][1] = 0.0f;
                P[m][jt][2] = 0.0f; P[m][jt][3] = 0.0f;
                MMA16816(P[m][jt], qh[m][0], qh[m][1], qh[m][2], qh[m][3], kh0, kh1);
                MMA16816(P[m][jt], ql[m][0], ql[m][1], ql[m][2], ql[m][3], kh0, kh1);
            }
        }
        uint32_t pa[2][4];
#pragma unroll
        for (int m = 0; m < 2; ++m) {
            float e00 = __expf(P[m][0][0]), e01 = __expf(P[m][0][1]);
            float e02 = __expf(P[m][0][2]), e03 = __expf(P[m][0][3]);
            float e10 = __expf(P[m][1][0]), e11 = __expf(P[m][1][1]);
            float e12 = __expf(P[m][1][2]), e13 = __expf(P[m][1][3]);
            sr[m] += (e00 + e01) + (e10 + e11);
            sr8[m] += (e02 + e03) + (e12 + e13);
            pa[m][0] = bf2u(__floats2bfloat162_rn(e00 - 1.0f, e01 - 1.0f));
            pa[m][1] = bf2u(__floats2bfloat162_rn(e02 - 1.0f, e03 - 1.0f));
            pa[m][2] = bf2u(__floats2bfloat162_rn(e10 - 1.0f, e11 - 1.0f));
            pa[m][3] = bf2u(__floats2bfloat162_rn(e12 - 1.0f, e13 - 1.0f));
        }
#pragma unroll
        for (int n = 0; n < 2; ++n) {
            uint32_t vh0, vh1;
            LDMX2(vh0, vh1, vbase + n * (8 * V8STR) + ks * 32);
#pragma unroll
            for (int m = 0; m < 2; ++m)
                MMA16816(o[m][n], pa[m][0], pa[m][1], pa[m][2], pa[m][3], vh0, vh1);
        }
    }
    const float* vs = (const float*)(smc + OVS);
#pragma unroll
    for (int m = 0; m < 2; ++m) {
        float s = sr[m], s8 = sr8[m];
        s += __shfl_xor_sync(0xffffffffu, s, 1);
        s += __shfl_xor_sync(0xffffffffu, s, 2);
        s8 += __shfl_xor_sync(0xffffffffu, s8, 1);
        s8 += __shfl_xor_sync(0xffffffffu, s8, 2);
        float ir = 1.0f / (s - 11.0f), ir8 = 1.0f / (s8 - 11.0f);
        int px0 = pg * 32 + m * 16 + rr;
#pragma unroll
        for (int n = 0; n < 2; ++n) {
            int c0 = h * 16 + n * 8 + q * 2;
            float cs0 = vs[c0], cs1 = vs[c0 + 1];
            uint32_t hi, lo;
            bfsplit((o[m][n][0] + cs0) * ir, (o[m][n][1] + cs1) * ir, hi, lo);
            *(uint32_t*)(smc + OXH + px0 * TSTR + c0 * 2) = hi;
            *(uint32_t*)(smc + OXL + px0 * TSTR + c0 * 2) = lo;
            bfsplit((o[m][n][2] + cs0) * ir8, (o[m][n][3] + cs1) * ir8, hi, lo);
            *(uint32_t*)(smc + OXH + (px0 + 8) * TSTR + c0 * 2) = hi;
            *(uint32_t*)(smc + OXL + (px0 + 8) * TSTR + c0 * 2) = lo;
        }
    }
    __syncthreads();   // O complete; KV dead
    {   // Wproj tiles (hi + lo) -> R2
        const float4* h4 = (const float4*)d_wph;
        const float4* l4 = (const float4*)d_wpl;
        float4* wh = (float4*)(smc + OW);
        float4* wl = (float4*)(smc + OW + TILEB);
        for (int i = tid; i < TILEB / 16; i += 1024) { wh[i] = h4[i]; wl[i] = l4[i]; }
    }
    __syncthreads();

    // ---- out-proj GEMM (3-chain): D[px][c] (A = O, B = Wproj) + bias ----
    hmma_gemm<true>(sb, OXH, OW, w, lane, D);
    {
        const float* bias = (const float*)(smc + OBI);
        int mt = w & 7, nq = w >> 3;
        int px0 = mt * 16 + rr;
        float* og = out + (((size_t)b * NC) << 14) + (y << 7);
#pragma unroll
        for (int n = 0; n < 4; ++n) {
            int c0 = nq * 32 + n * 8 + q * 2;
            float b0 = bias[c0], b1 = bias[c0 + 1];
            float* p0 = og + (((size_t)c0) << 14);
            float* p1 = og + (((size_t)(c0 + 1)) << 14);
            p0[px0] = D[n][0] + b0;
            p1[px0] = D[n][1] + b1;
            p0[px0 + 8] = D[n][2] + b0;
            p1[px0 + 8] = D[n][3] + b1;
        }
    }
}

// ----------------------------------------------------------------------------
extern "C" void kernel_launch(void* const* d_in, const int* in_sizes, int n_in,
                              void* d_out, int out_size) {
    const float* x     = (const float*)d_in[0];
    const float* Wq    = (const float*)d_in[1];
    const float* Wkv   = (const float*)d_in[2];
    const float* Wproj = (const float*)d_in[3];
    const float* bproj = (const float*)d_in[4];
    const float* dw    = (const float*)d_in[5];
    const float* pw    = (const float*)d_in[6];
    const float* lnw   = (const float*)d_in[7];
    const float* lnb   = (const float*)d_in[8];
    float* out = (float*)d_out;

    cudaFuncSetAttribute(k_main, cudaFuncAttributeMaxDynamicSharedMemorySize, SMB);

    k_prep<<<802, 256>>>(pw, Wkv, Wq, Wproj);
    k_pool_dw<<<NB * NC, 256>>>(x, dw);
    k_pw_ln_kv<<<NB * KVL, 256>>>(lnw, lnb);
    k_main<<<NB * 128, 1024, SMB>>>(x, bproj, out);
}

// round 17
// speedup vs baseline: 1.3241x; 1.1128x over previous
#include <cuda_runtime.h>
#include <cuda_bf16.h>
#include <math.h>
#include <stdint.h>

#define NB 8
#define NC 128
#define NH 8
#define HD 16
#define KVL 85

#define TSTR 272
#define TILEB (128 * TSTR)     // 34816
#define K8STR 272
#define K8TILE (96 * K8STR)    // 26112: rows=kv(96 pad), cols=8 heads x 16c
#define V8STR 208
#define V8TILE (128 * V8STR)   // 26624: rows=8 heads x 16c, cols=j(96 pad 104)

__device__ __align__(16) float d_tab[128 * 64];
__device__ __align__(16) float d_tabT[64 * 128];
__device__ __align__(16) float d_tabR[8 * 64];
__device__ __align__(16) float d_y1[NB * KVL * NC];
__device__ __align__(16) float d_pwT[128 * 128];
__device__ __align__(16) float d_WkvT[128 * 256];
__device__ __align__(16) float d_vsum[NB * 128];     // exact fp32 per-head V colsum
__device__ __align__(16) unsigned char d_wqh[TILEB];
__device__ __align__(16) unsigned char d_wph[TILEB];
__device__ __align__(16) unsigned char d_wpl[TILEB];
__device__ __align__(16) unsigned char d_kth[NB * K8TILE];
__device__ __align__(16) unsigned char d_vth[NB * V8TILE];

__device__ __forceinline__ uint32_t bf2u(__nv_bfloat162 v) {
    return ((uint32_t)__bfloat16_as_ushort(v.y) << 16) | (uint32_t)__bfloat16_as_ushort(v.x);
}
__device__ __forceinline__ void bfsplit(float v0, float v1, uint32_t& hi, uint32_t& lo) {
    __nv_bfloat162 hh = __floats2bfloat162_rn(v0, v1);
    __nv_bfloat162 ll = __floats2bfloat162_rn(v0 - __bfloat162float(hh.x),
                                              v1 - __bfloat162float(hh.y));
    hi = bf2u(hh); lo = bf2u(ll);
}

// ---------------- K0: tables + transposes + weight split + zeroing ----------
__global__ void k_prep(const float* __restrict__ pw, const float* __restrict__ Wkv,
                       const float* __restrict__ Wq, const float* __restrict__ Wp) {
    int idx = blockIdx.x * 256 + threadIdx.x;
    if (idx < 8192) {
        int yv = idx >> 6, j = idx & 63, i = j & 31;
        float inv = powf(10000.0f, -(2.0f * (float)i) / 64.0f);
        float a = (float)yv * inv;
        d_tab[idx] = (j < 32) ? sinf(a) : cosf(a);
    } else if (idx < 16384) {
        int e = idx - 8192;
        int j = e >> 7, p = e & 127, i = j & 31;
        float inv = powf(10000.0f, -(2.0f * (float)i) / 64.0f);
        float a = (float)p * inv;
        d_tabT[e] = (j < 32) ? sinf(a) : cosf(a);
    } else if (idx < 16896) {
        int e = idx - 16384;
        int bin = e >> 6, j = e & 63, i = j & 31;
        float inv = powf(10000.0f, -(2.0f * (float)i) / 64.0f);
        float s = 0.0f;
        for (int t = 0; t < 16; ++t) {
            float a = (float)(bin * 16 + t) * inv;
            s += (j < 32) ? sinf(a) : cosf(a);
        }
        d_tabR[e] = s;
    } else if (idx < 33280) {
        int e = idx - 16896;
        d_pwT[e] = pw[(e & 127) * 128 + (e >> 7)];
    } else if (idx < 66048) {
        int e = idx - 33280;
        d_WkvT[e] = Wkv[(e & 255) * 128 + (e >> 8)];
    } else if (idx < 98816) {
        int i = idx - 66048;
        int e;
        if (i < 16384) {           // Wq: hi tile only
            e = i;
            int o = e >> 7, c = e & 127;
            float v = Wq[e];
            *(__nv_bfloat16*)(d_wqh + (uint32_t)(o * TSTR + c * 2)) = __float2bfloat16(v);
        } else {                   // Wproj: hi + lo tiles
            e = i - 16384;
            int o = e >> 7, c = e & 127;
            float v = Wp[e];
            __nv_bfloat16 h = __float2bfloat16(v);
            uint32_t off = (uint32_t)(o * TSTR + c * 2);
            *(__nv_bfloat16*)(d_wph + off) = h;
            *(__nv_bfloat16*)(d_wpl + off) = __float2bfloat16(v - __bfloat162float(h));
        }
    } else if (idx < 98816 + 52224) {
        ((uint32_t*)d_kth)[idx - 98816] = 0;
    } else if (idx < 98816 + 52224 + 53248) {
        ((uint32_t*)d_vth)[idx - 98816 - 52224] = 0;
    } else if (idx < 98816 + 52224 + 53248 + 1024) {
        d_vsum[idx - 98816 - 52224 - 53248] = 0.0f;
    }
}

// ---------------- K1: ASPP pooling + depthwise conv (validated) -------------
__global__ void k_pool_dw(const float* __restrict__ x, const float* __restrict__ dw) {
    __shared__ float pm[64];
    __shared__ float g4[16];
    __shared__ float g2[4];
    __shared__ float g1[1];
    int tid = threadIdx.x;
    int b = blockIdx.x >> 7, c = blockIdx.x & 127;
    if (tid < 64) pm[tid] = 0.0f;
    __syncthreads();
    int r = tid >> 1, hf = tid & 1;
    const float4* xr = (const float4*)(x + ((size_t)(b * NC + c) << 14) + (r << 7) + (hf << 6));
    float sbin[4] = {0.0f, 0.0f, 0.0f, 0.0f};
#pragma unroll
    for (int q = 0; q < 16; ++q) {
        float4 v = xr[q];
        sbin[q >> 2] += (v.x + v.y) + (v.z + v.w);
    }
    int by = r >> 4;
#pragma unroll
    for (int t = 0; t < 4; ++t) atomicAdd(&pm[by * 8 + hf * 4 + t], sbin[t]);
    __syncthreads();
    if (tid < 64) {
        int byy = tid >> 3, bx = tid & 7;
        float pe = (c < 64) ? d_tabR[byy * 64 + c] : d_tabR[bx * 64 + (c - 64)];
        pm[tid] = (pm[tid] + 16.0f * pe) * (1.0f / 256.0f);
    }
    __syncthreads();
    if (tid < 16) {
        int i = tid >> 2, j = tid & 3;
        g4[tid] = 0.25f * (pm[(2 * i) * 8 + 2 * j] + pm[(2 * i) * 8 + 2 * j + 1] +
                           pm[(2 * i + 1) * 8 + 2 * j] + pm[(2 * i + 1) * 8 + 2 * j + 1]);
    } else if (tid < 20) {
        int t = tid - 16, i = t >> 1, j = t & 1;
        float s = 0.0f;
        for (int yy = 0; yy < 4; ++yy)
            for (int xq = 0; xq < 4; ++xq) s += pm[(4 * i + yy) * 8 + 4 * j + xq];
        g2[t] = s * (1.0f / 16.0f);
    } else if (tid == 20) {
        float s = 0.0f;
        for (int q = 0; q < 64; ++q) s += pm[q];
        g1[0] = s * (1.0f / 64.0f);
    }
    __syncthreads();
    if (tid < KVL) {
        float wv[9];
#pragma unroll
        for (int q = 0; q < 9; ++q) wv[q] = dw[c * 9 + q];
        const float* g; int s, ly, lx;
        if (tid < 64)      { g = pm; s = 8; ly = tid >> 3;        lx = tid & 7; }
        else if (tid < 80) { int t = tid - 64; g = g4; s = 4; ly = t >> 2; lx = t & 3; }
        else if (tid < 84) { int t = tid - 80; g = g2; s = 2; ly = t >> 1; lx = t & 1; }
        else               { g = g1; s = 1; ly = 0; lx = 0; }
        float a = 0.0f;
#pragma unroll
        for (int ky = 0; ky < 3; ++ky) {
            int iy = ly + ky - 1;
            bool oky = (iy >= 0) && (iy < s);
#pragma unroll
            for (int kx = 0; kx < 3; ++kx) {
                int ix = lx + kx - 1;
                if (oky && ix >= 0 && ix < s) a += g[iy * s + ix] * wv[ky * 3 + kx];
            }
        }
        d_y1[((size_t)b * KVL + tid) * NC + c] = a;
    }
}

// ---------------- K2: pointwise -> LN -> GELU -> KV proj + V colsum ---------
__global__ void k_pw_ln_kv(const float* __restrict__ lnw, const float* __restrict__ lnb) {
    __shared__ float ycol[128];
    __shared__ float part[256];
    __shared__ float zs[128];
    __shared__ float red[2];
    int tid = threadIdx.x;
    int b = blockIdx.x / KVL;
    int row = blockIdx.x - b * KVL;
    if (tid < 128) ycol[tid] = d_y1[((size_t)b * KVL + row) * NC + tid];
    __syncthreads();
    {
        int o = tid & 127, half = tid >> 7;
        const float* wc = d_pwT + (half << 6) * 128 + o;
        const float* yc = ycol + (half << 6);
        float a = 0.0f;
#pragma unroll 8
        for (int ci = 0; ci < 64; ++ci) a += wc[ci * 128] * yc[ci];
        part[tid] = a;
    }
    __syncthreads();
    if (tid < 128) zs[tid] = part[tid] + part[tid + 128];
    __syncthreads();
    if (tid < 32) {
        float s = zs[tid] + zs[tid + 32] + zs[tid + 64] + zs[tid + 96];
#pragma unroll
        for (int o = 16; o; o >>= 1) s += __shfl_xor_sync(0xffffffffu, s, o);
        if (tid == 0) red[0] = s * (1.0f / 128.0f);
    }
    __syncthreads();
    float mu = red[0];
    if (tid < 32) {
        float s = 0.0f;
#pragma unroll
        for (int q = 0; q < 4; ++q) { float dd = zs[tid + 32 * q] - mu; s += dd * dd; }
#pragma unroll
        for (int o = 16; o; o >>= 1) s += __shfl_xor_sync(0xffffffffu, s, o);
        if (tid == 0) red[1] = s * (1.0f / 128.0f);
    }
    __syncthreads();
    float rstd = rsqrtf(red[1] + 1e-5f);
    if (tid < 128) {
        float zn = (zs[tid] - mu) * rstd * lnw[tid] + lnb[tid];
        zs[tid] = 0.5f * zn * (1.0f + erff(zn * 0.70710678118654752f));
    }
    __syncthreads();
    float a = 0.0f;
    const float* wc = d_WkvT + tid;
#pragma unroll 8
    for (int ci = 0; ci < 128; ++ci) a += wc[ci * 256] * zs[ci];
    __nv_bfloat16 h = __float2bfloat16(a);
    if (tid < 128) {       // K hi only, rows=kv j, cols=head*16+d
        int m = tid >> 4, d = tid & 15;
        uint32_t off = ((uint32_t)b * 96 + row) * K8STR + m * 32 + d * 2;
        *(__nv_bfloat16*)(d_kth + off) = h;
    } else {               // V^T hi + exact fp32 colsum
        int cc = tid - 128;
        int m = cc >> 4, d = cc & 15;
        uint32_t off = ((uint32_t)b * 128 + m * 16 + d) * V8STR + row * 2;
        *(__nv_bfloat16*)(d_vth + off) = h;
        atomicAdd(&d_vsum[b * 128 + cc], a);
    }
}

// ---------------- K3: fused main — 1/1/3-chain HMMA, all fills up front -----
#define OXH 0                   // X-hi -> Q-hi -> O-hi
#define OXL TILEB               // Wq-hi -> O-lo
#define OK8H (2 * TILEB)        // K hi (resident)
#define OV8H (OK8H + K8TILE)    // V hi (resident)
#define OWP  (OV8H + V8TILE)    // Wproj hi (lo at +TILEB), resident
#define OBI  (OWP + 2 * TILEB)  // 192000
#define OVS  (OBI + 512)
#define SMB  (OVS + 512 + 64)   // 193088

#define LDMX4(r0, r1, r2, r3, a) \
    asm volatile("ldmatrix.sync.aligned.m8n8.x4.shared.b16 {%0,%1,%2,%3}, [%4];" \
        : "=r"(r0), "=r"(r1), "=r"(r2), "=r"(r3) : "r"(a))
#define LDMX2(r0, r1, a) \
    asm volatile("ldmatrix.sync.aligned.m8n8.x2.shared.b16 {%0,%1}, [%2];" \
        : "=r"(r0), "=r"(r1) : "r"(a))
#define MMA16816(d, a0, a1, a2, a3, b0, b1) \
    asm volatile("mma.sync.aligned.m16n8k16.row.col.f32.bf16.bf16.f32 " \
        "{%0,%1,%2,%3}, {%4,%5,%6,%7}, {%8,%9}, {%0,%1,%2,%3};" \
        : "+f"((d)[0]), "+f"((d)[1]), "+f"((d)[2]), "+f"((d)[3]) \
        : "r"(a0), "r"(a1), "r"(a2), "r"(a3), "r"(b0), "r"(b1))

// D[m=A-rows][n=B-rows]: 32 warps, mt=w&7 (16 A-rows), nq=w>>3 (32 B-rows)
// CH=1: AhBh. CH=2: +AlBh. CH=3: +AhBl.
template <int CH>
__device__ __forceinline__ void hmma_gemm(uint32_t sb, uint32_t aBase, uint32_t bBase,
                                          int w, int lane, float D[4][4]) {
#pragma unroll
    for (int n = 0; n < 4; ++n)
#pragma unroll
        for (int q = 0; q < 4; ++q) D[n][q] = 0.0f;
    int mt = w & 7, nq = w >> 3;
    int sub = lane >> 3, r = lane & 7;
    uint32_t aH = sb + aBase + (uint32_t)((mt * 16 + (sub & 1) * 8 + r) * TSTR + (sub >> 1) * 16);
    int bl = lane & 15;
    uint32_t bH = sb + bBase + (uint32_t)((nq * 32 + (bl & 7)) * TSTR + (bl >> 3) * 16);
#pragma unroll
    for (int kc = 0; kc < 8; ++kc) {
        uint32_t ah0, ah1, ah2, ah3;
        LDMX4(ah0, ah1, ah2, ah3, aH + kc * 32);
        uint32_t al0, al1, al2, al3;
        if (CH >= 2) LDMX4(al0, al1, al2, al3, aH + TILEB + kc * 32);
#pragma unroll
        for (int n = 0; n < 4; ++n) {
            uint32_t bh0, bh1;
            LDMX2(bh0, bh1, bH + n * (8 * TSTR) + kc * 32);
            MMA16816(D[n], ah0, ah1, ah2, ah3, bh0, bh1);
            if (CH >= 2) MMA16816(D[n], al0, al1, al2, al3, bh0, bh1);
            if (CH >= 3) {
                uint32_t bl0, bl1;
                LDMX2(bl0, bl1, bH + TILEB + n * (8 * TSTR) + kc * 32);
                MMA16816(D[n], ah0, ah1, ah2, ah3, bl0, bl1);
            }
        }
    }
}

__global__ void __launch_bounds__(1024, 1)
k_main(const float* __restrict__ x, const float* __restrict__ bproj,
       float* __restrict__ out) {
    extern __shared__ char smc[];
    uint32_t sb;
    asm("{ .reg .u64 t; cvta.to.shared.u64 t, %1; cvt.u32.u64 %0, t; }" : "=r"(sb) : "l"(smc));
    int tid = threadIdx.x, w = tid >> 5, lane = tid & 31;
    int b = blockIdx.x >> 7, y = blockIdx.x & 127;

    // ======== consolidated fills ========
    if (tid < 128) ((float*)(smc + OBI))[tid] = bproj[tid];
    else if (tid < 256) ((float*)(smc + OVS))[tid - 128] = d_vsum[b * 128 + tid - 128];
    {   // Wq-hi -> OXL
        const float4* h4 = (const float4*)d_wqh;
        float4* wh = (float4*)(smc + OXL);
        for (int i = tid; i < TILEB / 16; i += 1024) wh[i] = h4[i];
    }
    {   // Wproj hi+lo -> OWP
        const float4* h4 = (const float4*)d_wph;
        const float4* l4 = (const float4*)d_wpl;
        float4* wh = (float4*)(smc + OWP);
        float4* wl = (float4*)(smc + OWP + TILEB);
        for (int i = tid; i < TILEB / 16; i += 1024) { wh[i] = h4[i]; wl[i] = l4[i]; }
    }
    {   // K-hi / V-hi (all 8 heads)
        const float4* kh = (const float4*)(d_kth + (size_t)b * K8TILE);
        const float4* vh = (const float4*)(d_vth + (size_t)b * V8TILE);
        float4* dkh = (float4*)(smc + OK8H);
        float4* dvh = (float4*)(smc + OV8H);
        for (int i = tid; i < K8TILE / 16; i += 1024) dkh[i] = kh[i];
        for (int i = tid; i < V8TILE / 16; i += 1024) dvh[i] = vh[i];
    }
    {   // Xp bf16 (hi only) -> OXH: rows=px, cols=c
        int p = tid & 127;
        int yoff = y << 7;
        for (int g = tid >> 7; g < 64; g += 8) {
            int c0 = g * 2, c1 = c0 + 1;
            float v0 = x[((size_t)(b * NC + c0) << 14) + yoff + p];
            float v1 = x[((size_t)(b * NC + c1) << 14) + yoff + p];
            v0 += (c0 < 64) ? d_tab[y * 64 + c0] : d_tabT[(c0 - 64) * 128 + p];
            v1 += (c1 < 64) ? d_tab[y * 64 + c1] : d_tabT[(c1 - 64) * 128 + p];
            *(uint32_t*)(smc + OXH + (uint32_t)(p * TSTR + c0 * 2)) =
                bf2u(__floats2bfloat162_rn(v0, v1));
        }
    }
    __syncthreads();

    float D[4][4];
    // ---- Q-GEMM (1-chain): D[px][c] (A = X-hi @ OXH, B = Wq-hi @ OXL) ----
    hmma_gemm<1>(sb, OXH, OXL, w, lane, D);
    __syncthreads();   // X and Wq reads done

    int q = lane & 3, rr = lane >> 2;
    {   // stage Q-hi (x0.25) into OXH (overwrites X)
        int mt = w & 7, nq = w >> 3;
        int px0 = mt * 16 + rr;
#pragma unroll
        for (int n = 0; n < 4; ++n) {
            int c = nq * 32 + n * 8 + q * 2;
            *(uint32_t*)(smc + OXH + px0 * TSTR + c * 2) =
                bf2u(__floats2bfloat162_rn(D[n][0] * 0.25f, D[n][1] * 0.25f));
            *(uint32_t*)(smc + OXH + (px0 + 8) * TSTR + c * 2) =
                bf2u(__floats2bfloat162_rn(D[n][2] * 0.25f, D[n][3] * 0.25f));
        }
    }
    __syncthreads();

    // ---- attention: one task/warp = (head h = w&7, 32-px group pg = w>>3) ----
    int h = w & 7, pg = w >> 3;
    int sub = lane >> 3, r8 = lane & 7, bl = lane & 15;
    uint32_t qh[2][4];
#pragma unroll
    for (int m = 0; m < 2; ++m) {
        uint32_t qa = sb + OXH + (uint32_t)((pg * 32 + m * 16 + (sub & 1) * 8 + r8) * TSTR
                    + h * 32 + (sub >> 1) * 16);
        LDMX4(qh[m][0], qh[m][1], qh[m][2], qh[m][3], qa);
    }
    __syncthreads();   // all Q frags loaded before O overwrites OXH

    uint32_t kbase = sb + OK8H + (uint32_t)((bl & 7) * K8STR + h * 32 + (bl >> 3) * 16);
    uint32_t vbase = sb + OV8H + (uint32_t)((h * 16 + (bl & 7)) * V8STR + (bl >> 3) * 16);
    float o[2][2][4];
#pragma unroll
    for (int m = 0; m < 2; ++m)
#pragma unroll
        for (int n = 0; n < 2; ++n)
#pragma unroll
            for (int e = 0; e < 4; ++e) o[m][n][e] = 0.0f;
    float sr[2] = {0.0f, 0.0f}, sr8[2] = {0.0f, 0.0f};
#pragma unroll
    for (int ks = 0; ks < 6; ++ks) {
        float P[2][2][4];
#pragma unroll
        for (int jt = 0; jt < 2; ++jt) {
            uint32_t kh0, kh1;
            LDMX2(kh0, kh1, kbase + (2 * ks + jt) * (8 * K8STR));
#pragma unroll
            for (int m = 0; m < 2; ++m) {
                P[m][jt][0] = 0.0f; P[m][jt][1] = 0.0f;
                P[m][jt][2] = 0.0f; P[m][jt][3] = 0.0f;
                MMA16816(P[m][jt], qh[m][0], qh[m][1], qh[m][2], qh[m][3], kh0, kh1);
            }
        }
        uint32_t pa[2][4];
#pragma unroll
        for (int m = 0; m < 2; ++m) {
            float e00 = __expf(P[m][0][0]), e01 = __expf(P[m][0][1]);
            float e02 = __expf(P[m][0][2]), e03 = __expf(P[m][0][3]);
            float e10 = __expf(P[m][1][0]), e11 = __expf(P[m][1][1]);
            float e12 = __expf(P[m][1][2]), e13 = __expf(P[m][1][3]);
            sr[m] += (e00 + e01) + (e10 + e11);
            sr8[m] += (e02 + e03) + (e12 + e13);
            pa[m][0] = bf2u(__floats2bfloat162_rn(e00 - 1.0f, e01 - 1.0f));
            pa[m][1] = bf2u(__floats2bfloat162_rn(e02 - 1.0f, e03 - 1.0f));
            pa[m][2] = bf2u(__floats2bfloat162_rn(e10 - 1.0f, e11 - 1.0f));
            pa[m][3] = bf2u(__floats2bfloat162_rn(e12 - 1.0f, e13 - 1.0f));
        }
#pragma unroll
        for (int n = 0; n < 2; ++n) {
            uint32_t vh0, vh1;
            LDMX2(vh0, vh1, vbase + n * (8 * V8STR) + ks * 32);
#pragma unroll
            for (int m = 0; m < 2; ++m)
                MMA16816(o[m][n], pa[m][0], pa[m][1], pa[m][2], pa[m][3], vh0, vh1);
        }
    }
    const float* vs = (const float*)(smc + OVS);
#pragma unroll
    for (int m = 0; m < 2; ++m) {
        float s = sr[m], s8 = sr8[m];
        s += __shfl_xor_sync(0xffffffffu, s, 1);
        s += __shfl_xor_sync(0xffffffffu, s, 2);
        s8 += __shfl_xor_sync(0xffffffffu, s8, 1);
        s8 += __shfl_xor_sync(0xffffffffu, s8, 2);
        float ir = 1.0f / (s - 11.0f), ir8 = 1.0f / (s8 - 11.0f);
        int px0 = pg * 32 + m * 16 + rr;
#pragma unroll
        for (int n = 0; n < 2; ++n) {
            int c0 = h * 16 + n * 8 + q * 2;
            float cs0 = vs[c0], cs1 = vs[c0 + 1];
            uint32_t hi, lo;
            bfsplit((o[m][n][0] + cs0) * ir, (o[m][n][1] + cs1) * ir, hi, lo);
            *(uint32_t*)(smc + OXH + px0 * TSTR + c0 * 2) = hi;
            *(uint32_t*)(smc + OXL + px0 * TSTR + c0 * 2) = lo;
            bfsplit((o[m][n][2] + cs0) * ir8, (o[m][n][3] + cs1) * ir8, hi, lo);
            *(uint32_t*)(smc + OXH + (px0 + 8) * TSTR + c0 * 2) = hi;
            *(uint32_t*)(smc + OXL + (px0 + 8) * TSTR + c0 * 2) = lo;
        }
    }
    __syncthreads();   // O complete

    // ---- out-proj GEMM (3-chain): D[px][c] (A = O hi/lo, B = Wproj hi/lo) ----
    hmma_gemm<3>(sb, OXH, OWP, w, lane, D);
    {
        const float* bias = (const float*)(smc + OBI);
        int mt = w & 7, nq = w >> 3;
        int px0 = mt * 16 + rr;
        float* og = out + (((size_t)b * NC) << 14) + (y << 7);
#pragma unroll
        for (int n = 0; n < 4; ++n) {
            int c0 = nq * 32 + n * 8 + q * 2;
            float b0 = bias[c0], b1 = bias[c0 + 1];
            float* p0 = og + (((size_t)c0) << 14);
            float* p1 = og + (((size_t)(c0 + 1)) << 14);
            p0[px0] = D[n][0] + b0;
            p1[px0] = D[n][1] + b1;
            p0[px0 + 8] = D[n][2] + b0;
            p1[px0 + 8] = D[n][3] + b1;
        }
    }
}

// ----------------------------------------------------------------------------
extern "C" void kernel_launch(void* const* d_in, const int* in_sizes, int n_in,
                              void* d_out, int out_size) {
    const float* x     = (const float*)d_in[0];
    const float* Wq    = (const float*)d_in[1];
    const float* Wkv   = (const float*)d_in[2];
    const float* Wproj = (const float*)d_in[3];
    const float* bproj = (const float*)d_in[4];
    const float* dw    = (const float*)d_in[5];
    const float* pw    = (const float*)d_in[6];
    const float* lnw   = (const float*)d_in[7];
    const float* lnb   = (const float*)d_in[8];
    float* out = (float*)d_out;

    cudaFuncSetAttribute(k_main, cudaFuncAttributeMaxDynamicSharedMemorySize, SMB);

    k_prep<<<802, 256>>>(pw, Wkv, Wq, Wproj);
    k_pool_dw<<<NB * NC, 256>>>(x, dw);
    k_pw_ln_kv<<<NB * KVL, 256>>>(lnw, lnb);
    k_main<<<NB * 128, 1024, SMB>>>(x, bproj, out);
}